// round 13
// baseline (speedup 1.0000x reference)
#include <cuda_runtime.h>
#include <cuda_fp16.h>

// ---------------------------------------------------------------------------
// DeeperGCN round 13:
//  - k_am: aggregation FUSED into mlp1 tile kernel. Gather results hsplit
//    directly into A-fragment smem (lane k owns feats 2k,2k+1 = frag slot k).
//    Removes g_s write+read (25.6 MB/layer) + 1 launch/layer.
//  - pre-packed weight frags, fp16-split m16n8k16 GEMMs, fused preprocessing
// ---------------------------------------------------------------------------

#define NMAX 50048
#define EMAX 800000
typedef unsigned long long u64;
typedef unsigned int u32;

__device__ int2     g_edge[EMAX];
__device__ int      g_ssrc[EMAX];
__device__ int      g_deg[NMAX];
__device__ int      g_off[NMAX];
__device__ int      g_cur[NMAX];
__device__ int      g_part[64];
__device__ int      g_scan_done;
__device__ unsigned g_zh [NMAX * 32];     // half2 per entry (64 feats / row)
__device__ float    g_h  [NMAX * 64];
__device__ float    g_hid[NMAX * 128];
// pre-packed weight fragments: mats 0=enc, 1..3=W2_i (gemm type), 4..6=W1_i (mlp)
__device__ uint2    g_bph[7][2048];
__device__ uint2    g_bpl[7][2048];

__device__ __forceinline__ float ex2f(float x) {
    float r; asm("ex2.approx.f32 %0, %1;" : "=f"(r) : "f"(x)); return r;
}
__device__ __forceinline__ unsigned h2pack(float a, float b) {
    __half2 h = __floats2half2_rn(a, b);
    return *(unsigned*)&h;
}
__device__ __forceinline__ float2 h2unpack(unsigned u) {
    __half2 h = *(__half2*)&u;
    return __half22float2(h);
}
__device__ __forceinline__ void hsplit(float a, float b, u32 &hi, u32 &lo) {
    hi = h2pack(a, b);
    float2 f = h2unpack(hi);
    lo = h2pack(a - f.x, b - f.y);
}
__device__ __forceinline__ void mmah(float* d, const u32* a, u32 b0, u32 b1) {
    asm volatile(
        "mma.sync.aligned.m16n8k16.row.col.f32.f16.f16.f32 "
        "{%0,%1,%2,%3}, {%4,%5,%6,%7}, {%8,%9}, {%0,%1,%2,%3};"
        : "+f"(d[0]), "+f"(d[1]), "+f"(d[2]), "+f"(d[3])
        : "r"(a[0]), "r"(a[1]), "r"(a[2]), "r"(a[3]), "r"(b0), "r"(b1));
}

// ---------------------------------------------------------------------------
// k_pack: one-time fragment packing of all 7 weight matrices (32KB each)
// ---------------------------------------------------------------------------
__global__ __launch_bounds__(256) void k_pack(const float* __restrict__ encW,
                                              const float* __restrict__ W1,
                                              const float* __restrict__ W2) {
    __shared__ float sw[8192];
    int b = blockIdx.x;  // 0: enc, 1..3: W2_i, 4..6: W1_i
    const float* src = (b == 0) ? encW : (b < 4 ? W2 + (b - 1) * 8192
                                                : W1 + (b - 4) * 8192);
    int tid = threadIdx.x;
    const float4* s4 = (const float4*)src;
    #pragma unroll
    for (int i = 0; i < 8; i++)
        ((float4*)sw)[tid + i * 256] = __ldg(&s4[tid + i * 256]);
    __syncthreads();
    bool mlp = (b >= 4);
    #pragma unroll
    for (int i = 0; i < 8; i++) {
        int id = tid + i * 256;                 // 0..2047
        int ln = id & 31;
        int g = ln >> 2, t = ln & 3;
        int nf, ks, stride;
        if (!mlp) { nf = (id >> 5) & 7;  ks = id >> 8; stride = 64; }
        else      { nf = (id >> 5) & 15; ks = id >> 9; stride = 128; }
        int n = nf * 8 + g, k0 = ks * 16 + 2 * t;
        float w00 = sw[(k0)     * stride + n];
        float w01 = sw[(k0 + 1) * stride + n];
        float w10 = sw[(k0 + 8) * stride + n];
        float w11 = sw[(k0 + 9) * stride + n];
        u32 bh0, bl0, bh1, bl1;
        hsplit(w00, w01, bh0, bl0);
        hsplit(w10, w11, bh1, bl1);
        g_bph[b][id] = make_uint2(bh0, bh1);
        g_bpl[b][id] = make_uint2(bl0, bl1);
    }
}

// ---------------------------------------------------------------------------
// Edge preprocessing (unchanged)
// ---------------------------------------------------------------------------
__global__ void k_normcount(const void* __restrict__ raw, int E) {
    __shared__ int s_is64;
    int tid = threadIdx.x;
    if (tid < 32) {
        const int* w = (const int*)raw;
        int bad = 0;
        int lim = min(128, E);
        for (int i = tid; i < lim; i += 32) bad |= w[2 * i + 1];
        unsigned b = __ballot_sync(0xffffffffu, bad != 0);
        if (tid == 0) s_is64 = (b == 0) ? 1 : 0;
    }
    if (blockIdx.x == 0 && tid == 0) g_scan_done = 0;
    __syncthreads();
    int is64 = s_is64;
    int base = (blockIdx.x * blockDim.x + tid) * 4;
    if (base >= E) return;
    if (is64) {
        const long long* p = (const long long*)raw;
        #pragma unroll
        for (int j = 0; j < 4; j++) {
            int e = base + j;
            if (e < E) {
                int s = (int)p[e], d = (int)p[(size_t)E + e];
                g_edge[e] = make_int2(s, d);
                atomicAdd(&g_deg[d], 1);
            }
        }
    } else {
        const int* p = (const int*)raw;
        #pragma unroll
        for (int j = 0; j < 4; j++) {
            int e = base + j;
            if (e < E) {
                int s = p[e], d = p[(size_t)E + e];
                g_edge[e] = make_int2(s, d);
                atomicAdd(&g_deg[d], 1);
            }
        }
    }
}

__global__ void k_scan(int n) {
    __shared__ int wsum[32];
    __shared__ int amLast;
    __shared__ int pp[64];
    int tid = threadIdx.x;
    int i = blockIdx.x * 1024 + tid;
    int v = (i < n) ? g_deg[i] : 0;
    int lane = tid & 31, wid = tid >> 5;
    int s = v;
    #pragma unroll
    for (int o = 1; o < 32; o <<= 1) {
        int t = __shfl_up_sync(0xffffffffu, s, o);
        if (lane >= o) s += t;
    }
    if (lane == 31) wsum[wid] = s;
    __syncthreads();
    if (wid == 0) {
        int w = wsum[lane];
        #pragma unroll
        for (int o = 1; o < 32; o <<= 1) {
            int t = __shfl_up_sync(0xffffffffu, w, o);
            if (lane >= o) w += t;
        }
        wsum[lane] = w;
    }
    __syncthreads();
    int base = wid ? wsum[wid - 1] : 0;
    int excl = base + s - v;
    if (i < n) { g_off[i] = excl; g_cur[i] = excl; }
    if (tid == 1023) {
        g_part[blockIdx.x] = base + s;
        __threadfence();
        int t = atomicAdd(&g_scan_done, 1);
        amLast = (t == (int)gridDim.x - 1);
    }
    __syncthreads();
    if (amLast) {
        int P = gridDim.x;
        if (tid < 64) pp[tid] = (tid < P) ? g_part[tid] : 0;
        __syncthreads();
        if (tid == 0) {
            int acc = 0;
            for (int k = 0; k < P; k++) { int vv = pp[k]; pp[k] = acc; acc += vv; }
        }
        __syncthreads();
        if (tid < P) g_part[tid] = pp[tid];
    }
}

__global__ void k_scatter(int E) {
    int base = (blockIdx.x * blockDim.x + threadIdx.x) * 4;
    if (base >= E) return;
    #pragma unroll
    for (int j = 0; j < 4; j++) {
        int e = base + j;
        if (e < E) {
            int2 ed = g_edge[e];
            int pos = atomicAdd(&g_cur[ed.y], 1) + g_part[ed.y >> 10];
            g_ssrc[pos] = ed.x;
        }
    }
}

// ---------------------------------------------------------------------------
// gemmT: [N,128] @ [128,64] + bias (+residual, +LN epilogue, +head)
// fp16-split m16n8k16. 256 thr / 8 warps; tile 128 x 64; B frags pre-packed.
// modes: 0 encoder -> zh only; 1 -> h fp32 + zh = relu(LN); 2 -> out + head
// ---------------------------------------------------------------------------
#define GEMMT_U32 (2 * 128 * 68 + 2 * 4096 + 400)
#define GEMMT_SMEM (GEMMT_U32 * 4)
__global__ __launch_bounds__(256) void k_gemmT(
    const float* __restrict__ A, int mat,
    const float* __restrict__ bias, const float* __restrict__ lg,
    const float* __restrict__ lb, const float* __restrict__ lw,
    const float* __restrict__ lhb, float* __restrict__ h_out,
    float* __restrict__ z_out, int N, int addres, int mode) {
    extern __shared__ u32 smu[];
    u32*   Ah  = smu;                       // 128*68
    u32*   Al  = Ah + 128 * 68;             // 128*68
    uint2* Bh  = (uint2*)(Al + 128 * 68);   // 2048 uint2
    uint2* Bl  = Bh + 2048;                 // 2048 uint2
    float* bs  = (float*)(Bl + 2048);       // 64
    float* gs  = bs + 64;
    float* bb  = gs + 64;
    float* lws = bb + 64;                   // 208 (192 used)
    int tid = threadIdx.x;
    int r0 = blockIdx.x * 128;
    // stage A: hi/lo fp16 pairs, row-major kpairs, stride 68
    {
        const float4* a4 = (const float4*)A;
        #pragma unroll
        for (int i = 0; i < 16; i++) {
            int idx = tid + i * 256;                // 128 rows x 32 f4
            int row = idx >> 5, c = idx & 31;
            int grow = min(r0 + row, N - 1);
            float4 v = __ldg(&a4[(size_t)grow * 32 + c]);
            u32 h0, l0, h1, l1;
            hsplit(v.x, v.y, h0, l0);
            hsplit(v.z, v.w, h1, l1);
            *(uint2*)&Ah[row * 68 + 2 * c] = make_uint2(h0, h1);
            *(uint2*)&Al[row * 68 + 2 * c] = make_uint2(l0, l1);
        }
    }
    // stage B: coalesced copy of pre-packed fragments
    {
        const uint4* ph = (const uint4*)g_bph[mat];
        const uint4* pl = (const uint4*)g_bpl[mat];
        uint4* dh = (uint4*)Bh;
        uint4* dl = (uint4*)Bl;
        #pragma unroll
        for (int i = 0; i < 4; i++) {
            dh[tid + i * 256] = __ldg(&ph[tid + i * 256]);
            dl[tid + i * 256] = __ldg(&pl[tid + i * 256]);
        }
        if (tid < 64) {
            bs[tid] = bias[tid];
            if (mode) { gs[tid] = lg[tid]; bb[tid] = lb[tid]; }
        }
        if (mode == 2 && tid >= 64 && tid < 112)
            ((float4*)lws)[tid - 64] = ((const float4*)lw)[tid - 64];
    }
    __syncthreads();
    int warp = tid >> 5, lane = tid & 31;
    int g = lane >> 2, t = lane & 3;
    int wm = warp * 16;
    float acc[8][4];
    #pragma unroll
    for (int nf = 0; nf < 8; nf++)
        #pragma unroll
        for (int c = 0; c < 4; c++) acc[nf][c] = 0.f;
    int b0 = (wm + g) * 68, b1 = (wm + 8 + g) * 68;
    #pragma unroll
    for (int ks = 0; ks < 8; ks++) {
        int kp = ks * 8 + t;
        u32 ah[4], al[4];
        ah[0] = Ah[b0 + kp];     ah[1] = Ah[b1 + kp];
        ah[2] = Ah[b0 + kp + 4]; ah[3] = Ah[b1 + kp + 4];
        al[0] = Al[b0 + kp];     al[1] = Al[b1 + kp];
        al[2] = Al[b0 + kp + 4]; al[3] = Al[b1 + kp + 4];
        #pragma unroll
        for (int nf = 0; nf < 8; nf++) {
            uint2 bh = Bh[(ks * 8 + nf) * 32 + lane];
            uint2 bl = Bl[(ks * 8 + nf) * 32 + lane];
            mmah(acc[nf], ah, bl.x, bl.y);   // Ahi*Blo
            mmah(acc[nf], al, bh.x, bh.y);   // Alo*Bhi
            mmah(acc[nf], ah, bh.x, bh.y);   // Ahi*Bhi
        }
    }
    // epilogue: thread owns rows {wm+g, wm+8+g}, cols {8nf+2t, +1}
    #pragma unroll
    for (int rs = 0; rs < 2; rs++) {
        int rr = r0 + wm + g + rs * 8;
        bool ok = rr < N;
        float y[16];
        #pragma unroll
        for (int nf = 0; nf < 8; nf++) {
            float2 bv = *(float2*)&bs[8 * nf + 2 * t];
            y[2 * nf]     = acc[nf][rs * 2]     + bv.x;
            y[2 * nf + 1] = acc[nf][rs * 2 + 1] + bv.y;
        }
        if (addres && ok) {
            #pragma unroll
            for (int nf = 0; nf < 8; nf++) {
                float2 h = ((const float2*)h_out)[(size_t)rr * 32 + 4 * nf + t];
                y[2 * nf] += h.x; y[2 * nf + 1] += h.y;
            }
        }
        if (mode == 0) {
            if (ok) {
                #pragma unroll
                for (int nf = 0; nf < 8; nf++)
                    g_zh[(size_t)rr * 32 + 4 * nf + t] = h2pack(y[2 * nf], y[2 * nf + 1]);
            }
            continue;
        }
        if (mode == 1 && ok) {
            #pragma unroll
            for (int nf = 0; nf < 8; nf++) {
                float2 v; v.x = y[2 * nf]; v.y = y[2 * nf + 1];
                ((float2*)h_out)[(size_t)rr * 32 + 4 * nf + t] = v;
            }
        }
        float s = 0.f, q = 0.f;
        #pragma unroll
        for (int c = 0; c < 16; c++) { s += y[c]; q = fmaf(y[c], y[c], q); }
        s += __shfl_xor_sync(0xffffffffu, s, 1);
        q += __shfl_xor_sync(0xffffffffu, q, 1);
        s += __shfl_xor_sync(0xffffffffu, s, 2);
        q += __shfl_xor_sync(0xffffffffu, q, 2);
        float mu = s * (1.f / 64.f);
        float var = q * (1.f / 64.f) - mu * mu;
        float rsv = rsqrtf(var + 1e-5f);
        float o16[16];
        #pragma unroll
        for (int nf = 0; nf < 8; nf++) {
            float2 gv = *(float2*)&gs[8 * nf + 2 * t];
            float2 cv = *(float2*)&bb[8 * nf + 2 * t];
            o16[2 * nf]     = fmaxf((y[2 * nf]     - mu) * rsv * gv.x + cv.x, 0.f);
            o16[2 * nf + 1] = fmaxf((y[2 * nf + 1] - mu) * rsv * gv.y + cv.y, 0.f);
        }
        if (mode == 1) {
            if (ok) {
                #pragma unroll
                for (int nf = 0; nf < 8; nf++)
                    g_zh[(size_t)rr * 32 + 4 * nf + t] = h2pack(o16[2 * nf], o16[2 * nf + 1]);
            }
        } else {  // mode 2: final out + head
            if (ok) {
                #pragma unroll
                for (int nf = 0; nf < 8; nf++) {
                    float2 v; v.x = o16[2 * nf]; v.y = o16[2 * nf + 1];
                    ((float2*)z_out)[(size_t)rr * 32 + 4 * nf + t] = v;
                }
            }
            float p0 = 0.f, p1 = 0.f, p2 = 0.f;
            #pragma unroll
            for (int nf = 0; nf < 8; nf++) {
                int c0 = 8 * nf + 2 * t, c1 = c0 + 1;
                p0 = fmaf(o16[2 * nf], lws[c0 * 3 + 0], p0);
                p1 = fmaf(o16[2 * nf], lws[c0 * 3 + 1], p1);
                p2 = fmaf(o16[2 * nf], lws[c0 * 3 + 2], p2);
                p0 = fmaf(o16[2 * nf + 1], lws[c1 * 3 + 0], p0);
                p1 = fmaf(o16[2 * nf + 1], lws[c1 * 3 + 1], p1);
                p2 = fmaf(o16[2 * nf + 1], lws[c1 * 3 + 2], p2);
            }
            p0 += __shfl_xor_sync(0xffffffffu, p0, 1);
            p1 += __shfl_xor_sync(0xffffffffu, p1, 1);
            p2 += __shfl_xor_sync(0xffffffffu, p2, 1);
            p0 += __shfl_xor_sync(0xffffffffu, p0, 2);
            p1 += __shfl_xor_sync(0xffffffffu, p1, 2);
            p2 += __shfl_xor_sync(0xffffffffu, p2, 2);
            if (t == 0 && ok) {
                size_t base = (size_t)N * 64 + (size_t)rr * 3;
                z_out[base + 0] = p0 + __ldg(lhb + 0);
                z_out[base + 1] = p1 + __ldg(lhb + 1);
                z_out[base + 2] = p2 + __ldg(lhb + 2);
            }
        }
    }
}

// ---------------------------------------------------------------------------
// k_am: FUSED softmax-aggregation + mlp1 ([N,64]@[64,128] + LN + ReLU)
// 256 thr / 8 warps; tile 128 rows x 128 cols.
// Phase A: warp w aggregates rows [w*16, w*16+16); lane owns feats 2l,2l+1;
//          result hsplit directly into Ah/Al frag slot [row*36 + lane].
// Phase B: identical to former mlp1T MMA + LN/ReLU epilogue.
// ---------------------------------------------------------------------------
#define MLP1T_U32 (2 * 128 * 36 + 2 * 4096 + 384)
#define MLP1T_SMEM (MLP1T_U32 * 4)
__global__ __launch_bounds__(256) void k_am(
    const float* __restrict__ tp, int li, int mat,
    const float* __restrict__ bias, const float* __restrict__ lg,
    const float* __restrict__ lb, float* __restrict__ out, int N) {
    extern __shared__ u32 smu[];
    u32*   Ah = smu;                        // 128*36
    u32*   Al = Ah + 128 * 36;
    uint2* Bh = (uint2*)(Al + 128 * 36);    // 2048 uint2
    uint2* Bl = Bh + 2048;
    float* bs = (float*)(Bl + 2048);        // 128
    float* gs = bs + 128;
    float* bb = gs + 128;
    int tid = threadIdx.x;
    int r0 = blockIdx.x * 128;
    // stage B frags + params (coalesced)
    {
        const uint4* ph = (const uint4*)g_bph[mat];
        const uint4* pl = (const uint4*)g_bpl[mat];
        uint4* dh = (uint4*)Bh;
        uint4* dl = (uint4*)Bl;
        #pragma unroll
        for (int i = 0; i < 4; i++) {
            dh[tid + i * 256] = __ldg(&ph[tid + i * 256]);
            dl[tid + i * 256] = __ldg(&pl[tid + i * 256]);
        }
        if (tid < 128) { bs[tid] = bias[tid]; gs[tid] = lg[tid]; bb[tid] = lb[tid]; }
    }
    int warp = tid >> 5, lane = tid & 31;
    // Phase A: gather + aggregate 16 rows per warp, write frags
    {
        float tl = __ldg(tp + li) * 1.4426950408889634f;
        #pragma unroll 1
        for (int r = 0; r < 16; r++) {
            int row = warp * 16 + r;
            int rr = r0 + row;
            u32 hi = 0, lo = 0;
            if (rr < N) {
                int beg = g_off[rr] + g_part[rr >> 10];
                int dg = g_deg[rr];
                float se0 = 0.f, se1 = 0.f, sn0 = 0.f, sn1 = 0.f;
                #pragma unroll 4
                for (int j = 0; j < dg; j++) {
                    int s = __ldg(&g_ssrc[beg + j]);
                    float2 v = h2unpack(__ldg(&g_zh[(size_t)s * 32 + lane]));
                    float m0 = fmaxf(v.x, 0.f);
                    float m1 = fmaxf(v.y, 0.f);
                    float e0 = ex2f(m0 * tl);
                    float e1 = ex2f(m1 * tl);
                    se0 += e0; se1 += e1;
                    sn0 = fmaf(m0, e0, sn0);
                    sn1 = fmaf(m1, e1, sn1);
                }
                float2 zd = h2unpack(g_zh[(size_t)rr * 32 + lane]);
                float o0 = zd.x + fmaf(1e-7f, se0, sn0) / (se0 + 1e-16f);
                float o1 = zd.y + fmaf(1e-7f, se1, sn1) / (se1 + 1e-16f);
                hsplit(o0, o1, hi, lo);
            }
            Ah[row * 36 + lane] = hi;
            Al[row * 36 + lane] = lo;
        }
    }
    __syncthreads();
    // Phase B: MMA + epilogue (as former mlp1T)
    int g = lane >> 2, t = lane & 3;
    int wm = warp * 16;
    float acc[16][4];
    #pragma unroll
    for (int nf = 0; nf < 16; nf++)
        #pragma unroll
        for (int c = 0; c < 4; c++) acc[nf][c] = 0.f;
    int b0 = (wm + g) * 36, b1 = (wm + 8 + g) * 36;
    #pragma unroll
    for (int ks = 0; ks < 4; ks++) {
        int kp = ks * 8 + t;
        u32 ah[4], al[4];
        ah[0] = Ah[b0 + kp];     ah[1] = Ah[b1 + kp];
        ah[2] = Ah[b0 + kp + 4]; ah[3] = Ah[b1 + kp + 4];
        al[0] = Al[b0 + kp];     al[1] = Al[b1 + kp];
        al[2] = Al[b0 + kp + 4]; al[3] = Al[b1 + kp + 4];
        #pragma unroll
        for (int nf = 0; nf < 16; nf++) {
            uint2 bh = Bh[(ks * 16 + nf) * 32 + lane];
            uint2 bl = Bl[(ks * 16 + nf) * 32 + lane];
            mmah(acc[nf], ah, bl.x, bl.y);
            mmah(acc[nf], al, bh.x, bh.y);
            mmah(acc[nf], ah, bh.x, bh.y);
        }
    }
    #pragma unroll
    for (int rs = 0; rs < 2; rs++) {
        int rr = r0 + wm + g + rs * 8;
        float y[32];
        #pragma unroll
        for (int nf = 0; nf < 16; nf++) {
            float2 bv = *(float2*)&bs[8 * nf + 2 * t];
            y[2 * nf]     = acc[nf][rs * 2]     + bv.x;
            y[2 * nf + 1] = acc[nf][rs * 2 + 1] + bv.y;
        }
        float s = 0.f, q = 0.f;
        #pragma unroll
        for (int c = 0; c < 32; c++) { s += y[c]; q = fmaf(y[c], y[c], q); }
        s += __shfl_xor_sync(0xffffffffu, s, 1);
        q += __shfl_xor_sync(0xffffffffu, q, 1);
        s += __shfl_xor_sync(0xffffffffu, s, 2);
        q += __shfl_xor_sync(0xffffffffu, q, 2);
        float mu = s * (1.f / 128.f);
        float var = q * (1.f / 128.f) - mu * mu;
        float rsv = rsqrtf(var + 1e-5f);
        if (rr < N) {
            #pragma unroll
            for (int nf = 0; nf < 16; nf++) {
                float2 gv = *(float2*)&gs[8 * nf + 2 * t];
                float2 cv = *(float2*)&bb[8 * nf + 2 * t];
                float2 v;
                v.x = fmaxf((y[2 * nf]     - mu) * rsv * gv.x + cv.x, 0.f);
                v.y = fmaxf((y[2 * nf + 1] - mu) * rsv * gv.y + cv.y, 0.f);
                ((float2*)out)[(size_t)rr * 64 + 4 * nf + t] = v;
            }
        }
    }
}

// ---------------------------------------------------------------------------
// Host launch
// ---------------------------------------------------------------------------
extern "C" void kernel_launch(void* const* d_in, const int* in_sizes, int n_in,
                              void* d_out, int out_size) {
    const float* x    = (const float*)d_in[0];
    const void*  ei   = d_in[1];
    const float* encW = (const float*)d_in[2];
    const float* encB = (const float*)d_in[3];
    const float* t    = (const float*)d_in[4];
    const float* W1   = (const float*)d_in[5];
    const float* b1   = (const float*)d_in[6];
    const float* g1   = (const float*)d_in[7];
    const float* bb1  = (const float*)d_in[8];
    const float* W2   = (const float*)d_in[9];
    const float* b2   = (const float*)d_in[10];
    const float* ng   = (const float*)d_in[11];
    const float* nb   = (const float*)d_in[12];
    const float* lw   = (const float*)d_in[13];
    const float* lb   = (const float*)d_in[14];
    int N = in_sizes[0] / 128;
    int E = in_sizes[1] / 2;
    if (N > NMAX) N = NMAX;
    if (E > EMAX) E = EMAX;
    float* out = (float*)d_out;

    cudaFuncSetAttribute(k_am,    cudaFuncAttributeMaxDynamicSharedMemorySize, MLP1T_SMEM);
    cudaFuncSetAttribute(k_gemmT, cudaFuncAttributeMaxDynamicSharedMemorySize, GEMMT_SMEM);

    float *gh, *ghid;
    int *gdeg;
    cudaGetSymbolAddress((void**)&gh,   g_h);
    cudaGetSymbolAddress((void**)&ghid, g_hid);
    cudaGetSymbolAddress((void**)&gdeg, g_deg);

    int eb4     = (E + 1023) / 1024;
    int tilesB  = (N + 127) / 128;
    int sblocks = (N + 1023) / 1024;

    // edge preprocessing (CSR by dst)
    cudaMemsetAsync(gdeg, 0, (size_t)N * sizeof(int));
    k_normcount<<<eb4, 256>>>(ei, E);
    // one-time weight fragment packing (overlaps with scan/scatter)
    k_pack<<<7, 256>>>(encW, W1, W2);
    k_scan<<<sblocks, 1024>>>(N);
    k_scatter<<<eb4, 256>>>(E);

    // encoder: x @ encW + encB -> zh (mode 0, mat 0)
    k_gemmT<<<tilesB, 256, GEMMT_SMEM>>>(x, 0, encB, nullptr, nullptr,
                                         nullptr, nullptr, gh, nullptr, N, 0, 0);

    for (int i = 0; i < 3; i++) {
        // fused aggr + mlp1 -> ghid
        k_am<<<tilesB, 256, MLP1T_SMEM>>>(t, i, 4 + i, b1 + i * 128,
                                          g1 + i * 128, bb1 + i * 128, ghid, N);
        if (i < 2) {
            // mlp2 (+res if i>0) -> gh fp32; zh = relu(LN(gh, ng[i+1]))
            k_gemmT<<<tilesB, 256, GEMMT_SMEM>>>(ghid, 1 + i, b2 + i * 64,
                                                 ng + (i + 1) * 64, nb + (i + 1) * 64,
                                                 nullptr, nullptr, gh, nullptr,
                                                 N, i ? 1 : 0, 1);
        } else {
            // last: res + final LN(ng[0]) + ReLU -> out, head -> out tail
            k_gemmT<<<tilesB, 256, GEMMT_SMEM>>>(ghid, 1 + i, b2 + i * 64,
                                                 ng, nb, lw, lb, gh, out, N, 1, 2);
        }
    }
}

// round 14
// speedup vs baseline: 1.5343x; 1.5343x over previous
#include <cuda_runtime.h>
#include <cuda_fp16.h>

// ---------------------------------------------------------------------------
// DeeperGCN round 14: r12 structure (best: 247.9us) + half-warp gather.
//  - k_aggr: 16 lanes per dst row, uint2 loads (4 feats/lane) -> half the
//    gather instructions, 2 independent row chains per warp (latency-bound fix)
//  - pre-packed weight frags, fp16-split m16n8k16 GEMMs, fused preprocessing
// ---------------------------------------------------------------------------

#define NMAX 50048
#define EMAX 800000
typedef unsigned long long u64;
typedef unsigned int u32;

__device__ int2     g_edge[EMAX];
__device__ int      g_ssrc[EMAX];
__device__ int      g_deg[NMAX];
__device__ int      g_off[NMAX];
__device__ int      g_cur[NMAX];
__device__ int      g_part[64];
__device__ int      g_scan_done;
__device__ unsigned g_zh [NMAX * 32];     // half2 per entry (64 feats / row)
__device__ float    g_h  [NMAX * 64];
__device__ float    g_s  [NMAX * 64];
__device__ float    g_hid[NMAX * 128];
// pre-packed weight fragments: mats 0=enc, 1..3=W2_i (gemm type), 4..6=W1_i (mlp)
__device__ uint2    g_bph[7][2048];
__device__ uint2    g_bpl[7][2048];

__device__ __forceinline__ float ex2f(float x) {
    float r; asm("ex2.approx.f32 %0, %1;" : "=f"(r) : "f"(x)); return r;
}
__device__ __forceinline__ unsigned h2pack(float a, float b) {
    __half2 h = __floats2half2_rn(a, b);
    return *(unsigned*)&h;
}
__device__ __forceinline__ float2 h2unpack(unsigned u) {
    __half2 h = *(__half2*)&u;
    return __half22float2(h);
}
__device__ __forceinline__ void hsplit(float a, float b, u32 &hi, u32 &lo) {
    hi = h2pack(a, b);
    float2 f = h2unpack(hi);
    lo = h2pack(a - f.x, b - f.y);
}
__device__ __forceinline__ void mmah(float* d, const u32* a, u32 b0, u32 b1) {
    asm volatile(
        "mma.sync.aligned.m16n8k16.row.col.f32.f16.f16.f32 "
        "{%0,%1,%2,%3}, {%4,%5,%6,%7}, {%8,%9}, {%0,%1,%2,%3};"
        : "+f"(d[0]), "+f"(d[1]), "+f"(d[2]), "+f"(d[3])
        : "r"(a[0]), "r"(a[1]), "r"(a[2]), "r"(a[3]), "r"(b0), "r"(b1));
}

// ---------------------------------------------------------------------------
// k_pack: one-time fragment packing of all 7 weight matrices (32KB each)
// ---------------------------------------------------------------------------
__global__ __launch_bounds__(256) void k_pack(const float* __restrict__ encW,
                                              const float* __restrict__ W1,
                                              const float* __restrict__ W2) {
    __shared__ float sw[8192];
    int b = blockIdx.x;  // 0: enc, 1..3: W2_i, 4..6: W1_i
    const float* src = (b == 0) ? encW : (b < 4 ? W2 + (b - 1) * 8192
                                                : W1 + (b - 4) * 8192);
    int tid = threadIdx.x;
    const float4* s4 = (const float4*)src;
    #pragma unroll
    for (int i = 0; i < 8; i++)
        ((float4*)sw)[tid + i * 256] = __ldg(&s4[tid + i * 256]);
    __syncthreads();
    bool mlp = (b >= 4);
    #pragma unroll
    for (int i = 0; i < 8; i++) {
        int id = tid + i * 256;                 // 0..2047
        int ln = id & 31;
        int g = ln >> 2, t = ln & 3;
        int nf, ks, stride;
        if (!mlp) { nf = (id >> 5) & 7;  ks = id >> 8; stride = 64; }
        else      { nf = (id >> 5) & 15; ks = id >> 9; stride = 128; }
        int n = nf * 8 + g, k0 = ks * 16 + 2 * t;
        float w00 = sw[(k0)     * stride + n];
        float w01 = sw[(k0 + 1) * stride + n];
        float w10 = sw[(k0 + 8) * stride + n];
        float w11 = sw[(k0 + 9) * stride + n];
        u32 bh0, bl0, bh1, bl1;
        hsplit(w00, w01, bh0, bl0);
        hsplit(w10, w11, bh1, bl1);
        g_bph[b][id] = make_uint2(bh0, bh1);
        g_bpl[b][id] = make_uint2(bl0, bl1);
    }
}

// ---------------------------------------------------------------------------
// Edge preprocessing (r12, unchanged)
// ---------------------------------------------------------------------------
__global__ void k_normcount(const void* __restrict__ raw, int E) {
    __shared__ int s_is64;
    int tid = threadIdx.x;
    if (tid < 32) {
        const int* w = (const int*)raw;
        int bad = 0;
        int lim = min(128, E);
        for (int i = tid; i < lim; i += 32) bad |= w[2 * i + 1];
        unsigned b = __ballot_sync(0xffffffffu, bad != 0);
        if (tid == 0) s_is64 = (b == 0) ? 1 : 0;
    }
    if (blockIdx.x == 0 && tid == 0) g_scan_done = 0;
    __syncthreads();
    int is64 = s_is64;
    int base = (blockIdx.x * blockDim.x + tid) * 4;
    if (base >= E) return;
    if (is64) {
        const long long* p = (const long long*)raw;
        #pragma unroll
        for (int j = 0; j < 4; j++) {
            int e = base + j;
            if (e < E) {
                int s = (int)p[e], d = (int)p[(size_t)E + e];
                g_edge[e] = make_int2(s, d);
                atomicAdd(&g_deg[d], 1);
            }
        }
    } else {
        const int* p = (const int*)raw;
        #pragma unroll
        for (int j = 0; j < 4; j++) {
            int e = base + j;
            if (e < E) {
                int s = p[e], d = p[(size_t)E + e];
                g_edge[e] = make_int2(s, d);
                atomicAdd(&g_deg[d], 1);
            }
        }
    }
}

__global__ void k_scan(int n) {
    __shared__ int wsum[32];
    __shared__ int amLast;
    __shared__ int pp[64];
    int tid = threadIdx.x;
    int i = blockIdx.x * 1024 + tid;
    int v = (i < n) ? g_deg[i] : 0;
    int lane = tid & 31, wid = tid >> 5;
    int s = v;
    #pragma unroll
    for (int o = 1; o < 32; o <<= 1) {
        int t = __shfl_up_sync(0xffffffffu, s, o);
        if (lane >= o) s += t;
    }
    if (lane == 31) wsum[wid] = s;
    __syncthreads();
    if (wid == 0) {
        int w = wsum[lane];
        #pragma unroll
        for (int o = 1; o < 32; o <<= 1) {
            int t = __shfl_up_sync(0xffffffffu, w, o);
            if (lane >= o) w += t;
        }
        wsum[lane] = w;
    }
    __syncthreads();
    int base = wid ? wsum[wid - 1] : 0;
    int excl = base + s - v;
    if (i < n) { g_off[i] = excl; g_cur[i] = excl; }
    if (tid == 1023) {
        g_part[blockIdx.x] = base + s;
        __threadfence();
        int t = atomicAdd(&g_scan_done, 1);
        amLast = (t == (int)gridDim.x - 1);
    }
    __syncthreads();
    if (amLast) {
        int P = gridDim.x;
        if (tid < 64) pp[tid] = (tid < P) ? g_part[tid] : 0;
        __syncthreads();
        if (tid == 0) {
            int acc = 0;
            for (int k = 0; k < P; k++) { int vv = pp[k]; pp[k] = acc; acc += vv; }
        }
        __syncthreads();
        if (tid < P) g_part[tid] = pp[tid];
    }
}

__global__ void k_scatter(int E) {
    int base = (blockIdx.x * blockDim.x + threadIdx.x) * 4;
    if (base >= E) return;
    #pragma unroll
    for (int j = 0; j < 4; j++) {
        int e = base + j;
        if (e < E) {
            int2 ed = g_edge[e];
            int pos = atomicAdd(&g_cur[ed.y], 1) + g_part[ed.y >> 10];
            g_ssrc[pos] = ed.x;
        }
    }
}

// ---------------------------------------------------------------------------
// Softmax aggregation: HALF-WARP (16 lanes) per dst row; lane owns 4 feats
// via one uint2 (2 half2) load. 2 independent row chains per warp.
// Per-feature summation order identical to r12 -> bit-identical results.
// ---------------------------------------------------------------------------
__global__ void k_aggr(const float* __restrict__ tp, int li,
                       float* __restrict__ so, int N) {
    int idx = blockIdx.x * blockDim.x + threadIdx.x;
    int row = idx >> 4;
    int l = idx & 15;
    if (row >= N) return;
    float tl = __ldg(tp + li) * 1.4426950408889634f;
    int beg = g_off[row] + g_part[row >> 10];
    int dg = g_deg[row];
    const uint2* zh2 = (const uint2*)g_zh;
    float se0 = 0.f, se1 = 0.f, se2 = 0.f, se3 = 0.f;
    float sn0 = 0.f, sn1 = 0.f, sn2 = 0.f, sn3 = 0.f;
    #pragma unroll 4
    for (int j = 0; j < dg; j++) {
        int s = __ldg(&g_ssrc[beg + j]);
        uint2 u = __ldg(&zh2[(size_t)s * 16 + l]);
        float2 va = h2unpack(u.x);
        float2 vb = h2unpack(u.y);
        float m0 = fmaxf(va.x, 0.f), m1 = fmaxf(va.y, 0.f);
        float m2 = fmaxf(vb.x, 0.f), m3 = fmaxf(vb.y, 0.f);
        float e0 = ex2f(m0 * tl), e1 = ex2f(m1 * tl);
        float e2 = ex2f(m2 * tl), e3 = ex2f(m3 * tl);
        se0 += e0; se1 += e1; se2 += e2; se3 += e3;
        sn0 = fmaf(m0, e0, sn0); sn1 = fmaf(m1, e1, sn1);
        sn2 = fmaf(m2, e2, sn2); sn3 = fmaf(m3, e3, sn3);
    }
    uint2 ud = zh2[(size_t)row * 16 + l];
    float2 za = h2unpack(ud.x), zb = h2unpack(ud.y);
    float4 o;
    o.x = za.x + fmaf(1e-7f, se0, sn0) / (se0 + 1e-16f);
    o.y = za.y + fmaf(1e-7f, se1, sn1) / (se1 + 1e-16f);
    o.z = zb.x + fmaf(1e-7f, se2, sn2) / (se2 + 1e-16f);
    o.w = zb.y + fmaf(1e-7f, se3, sn3) / (se3 + 1e-16f);
    ((float4*)so)[(size_t)row * 16 + l] = o;
}

// ---------------------------------------------------------------------------
// gemmT: [N,128] @ [128,64] + bias (+residual, +LN epilogue, +head)
// fp16-split m16n8k16. 256 thr / 8 warps; tile 128 x 64; B frags pre-packed.
// modes: 0 encoder -> zh only; 1 -> h fp32 + zh = relu(LN); 2 -> out + head
// ---------------------------------------------------------------------------
#define GEMMT_U32 (2 * 128 * 68 + 2 * 4096 + 400)
#define GEMMT_SMEM (GEMMT_U32 * 4)
__global__ __launch_bounds__(256) void k_gemmT(
    const float* __restrict__ A, int mat,
    const float* __restrict__ bias, const float* __restrict__ lg,
    const float* __restrict__ lb, const float* __restrict__ lw,
    const float* __restrict__ lhb, float* __restrict__ h_out,
    float* __restrict__ z_out, int N, int addres, int mode) {
    extern __shared__ u32 smu[];
    u32*   Ah  = smu;                       // 128*68
    u32*   Al  = Ah + 128 * 68;             // 128*68
    uint2* Bh  = (uint2*)(Al + 128 * 68);   // 2048 uint2
    uint2* Bl  = Bh + 2048;                 // 2048 uint2
    float* bs  = (float*)(Bl + 2048);       // 64
    float* gs  = bs + 64;
    float* bb  = gs + 64;
    float* lws = bb + 64;                   // 208 (192 used)
    int tid = threadIdx.x;
    int r0 = blockIdx.x * 128;
    // stage A: hi/lo fp16 pairs, row-major kpairs, stride 68
    {
        const float4* a4 = (const float4*)A;
        #pragma unroll
        for (int i = 0; i < 16; i++) {
            int idx = tid + i * 256;                // 128 rows x 32 f4
            int row = idx >> 5, c = idx & 31;
            int grow = min(r0 + row, N - 1);
            float4 v = __ldg(&a4[(size_t)grow * 32 + c]);
            u32 h0, l0, h1, l1;
            hsplit(v.x, v.y, h0, l0);
            hsplit(v.z, v.w, h1, l1);
            *(uint2*)&Ah[row * 68 + 2 * c] = make_uint2(h0, h1);
            *(uint2*)&Al[row * 68 + 2 * c] = make_uint2(l0, l1);
        }
    }
    // stage B: coalesced copy of pre-packed fragments
    {
        const uint4* ph = (const uint4*)g_bph[mat];
        const uint4* pl = (const uint4*)g_bpl[mat];
        uint4* dh = (uint4*)Bh;
        uint4* dl = (uint4*)Bl;
        #pragma unroll
        for (int i = 0; i < 4; i++) {
            dh[tid + i * 256] = __ldg(&ph[tid + i * 256]);
            dl[tid + i * 256] = __ldg(&pl[tid + i * 256]);
        }
        if (tid < 64) {
            bs[tid] = bias[tid];
            if (mode) { gs[tid] = lg[tid]; bb[tid] = lb[tid]; }
        }
        if (mode == 2 && tid >= 64 && tid < 112)
            ((float4*)lws)[tid - 64] = ((const float4*)lw)[tid - 64];
    }
    __syncthreads();
    int warp = tid >> 5, lane = tid & 31;
    int g = lane >> 2, t = lane & 3;
    int wm = warp * 16;
    float acc[8][4];
    #pragma unroll
    for (int nf = 0; nf < 8; nf++)
        #pragma unroll
        for (int c = 0; c < 4; c++) acc[nf][c] = 0.f;
    int b0 = (wm + g) * 68, b1 = (wm + 8 + g) * 68;
    #pragma unroll
    for (int ks = 0; ks < 8; ks++) {
        int kp = ks * 8 + t;
        u32 ah[4], al[4];
        ah[0] = Ah[b0 + kp];     ah[1] = Ah[b1 + kp];
        ah[2] = Ah[b0 + kp + 4]; ah[3] = Ah[b1 + kp + 4];
        al[0] = Al[b0 + kp];     al[1] = Al[b1 + kp];
        al[2] = Al[b0 + kp + 4]; al[3] = Al[b1 + kp + 4];
        #pragma unroll
        for (int nf = 0; nf < 8; nf++) {
            uint2 bh = Bh[(ks * 8 + nf) * 32 + lane];
            uint2 bl = Bl[(ks * 8 + nf) * 32 + lane];
            mmah(acc[nf], ah, bl.x, bl.y);   // Ahi*Blo
            mmah(acc[nf], al, bh.x, bh.y);   // Alo*Bhi
            mmah(acc[nf], ah, bh.x, bh.y);   // Ahi*Bhi
        }
    }
    // epilogue: thread owns rows {wm+g, wm+8+g}, cols {8nf+2t, +1}
    #pragma unroll
    for (int rs = 0; rs < 2; rs++) {
        int rr = r0 + wm + g + rs * 8;
        bool ok = rr < N;
        float y[16];
        #pragma unroll
        for (int nf = 0; nf < 8; nf++) {
            float2 bv = *(float2*)&bs[8 * nf + 2 * t];
            y[2 * nf]     = acc[nf][rs * 2]     + bv.x;
            y[2 * nf + 1] = acc[nf][rs * 2 + 1] + bv.y;
        }
        if (addres && ok) {
            #pragma unroll
            for (int nf = 0; nf < 8; nf++) {
                float2 h = ((const float2*)h_out)[(size_t)rr * 32 + 4 * nf + t];
                y[2 * nf] += h.x; y[2 * nf + 1] += h.y;
            }
        }
        if (mode == 0) {
            if (ok) {
                #pragma unroll
                for (int nf = 0; nf < 8; nf++)
                    g_zh[(size_t)rr * 32 + 4 * nf + t] = h2pack(y[2 * nf], y[2 * nf + 1]);
            }
            continue;
        }
        if (mode == 1 && ok) {
            #pragma unroll
            for (int nf = 0; nf < 8; nf++) {
                float2 v; v.x = y[2 * nf]; v.y = y[2 * nf + 1];
                ((float2*)h_out)[(size_t)rr * 32 + 4 * nf + t] = v;
            }
        }
        float s = 0.f, q = 0.f;
        #pragma unroll
        for (int c = 0; c < 16; c++) { s += y[c]; q = fmaf(y[c], y[c], q); }
        s += __shfl_xor_sync(0xffffffffu, s, 1);
        q += __shfl_xor_sync(0xffffffffu, q, 1);
        s += __shfl_xor_sync(0xffffffffu, s, 2);
        q += __shfl_xor_sync(0xffffffffu, q, 2);
        float mu = s * (1.f / 64.f);
        float var = q * (1.f / 64.f) - mu * mu;
        float rsv = rsqrtf(var + 1e-5f);
        float o16[16];
        #pragma unroll
        for (int nf = 0; nf < 8; nf++) {
            float2 gv = *(float2*)&gs[8 * nf + 2 * t];
            float2 cv = *(float2*)&bb[8 * nf + 2 * t];
            o16[2 * nf]     = fmaxf((y[2 * nf]     - mu) * rsv * gv.x + cv.x, 0.f);
            o16[2 * nf + 1] = fmaxf((y[2 * nf + 1] - mu) * rsv * gv.y + cv.y, 0.f);
        }
        if (mode == 1) {
            if (ok) {
                #pragma unroll
                for (int nf = 0; nf < 8; nf++)
                    g_zh[(size_t)rr * 32 + 4 * nf + t] = h2pack(o16[2 * nf], o16[2 * nf + 1]);
            }
        } else {  // mode 2: final out + head
            if (ok) {
                #pragma unroll
                for (int nf = 0; nf < 8; nf++) {
                    float2 v; v.x = o16[2 * nf]; v.y = o16[2 * nf + 1];
                    ((float2*)z_out)[(size_t)rr * 32 + 4 * nf + t] = v;
                }
            }
            float p0 = 0.f, p1 = 0.f, p2 = 0.f;
            #pragma unroll
            for (int nf = 0; nf < 8; nf++) {
                int c0 = 8 * nf + 2 * t, c1 = c0 + 1;
                p0 = fmaf(o16[2 * nf], lws[c0 * 3 + 0], p0);
                p1 = fmaf(o16[2 * nf], lws[c0 * 3 + 1], p1);
                p2 = fmaf(o16[2 * nf], lws[c0 * 3 + 2], p2);
                p0 = fmaf(o16[2 * nf + 1], lws[c1 * 3 + 0], p0);
                p1 = fmaf(o16[2 * nf + 1], lws[c1 * 3 + 1], p1);
                p2 = fmaf(o16[2 * nf + 1], lws[c1 * 3 + 2], p2);
            }
            p0 += __shfl_xor_sync(0xffffffffu, p0, 1);
            p1 += __shfl_xor_sync(0xffffffffu, p1, 1);
            p2 += __shfl_xor_sync(0xffffffffu, p2, 1);
            p0 += __shfl_xor_sync(0xffffffffu, p0, 2);
            p1 += __shfl_xor_sync(0xffffffffu, p1, 2);
            p2 += __shfl_xor_sync(0xffffffffu, p2, 2);
            if (t == 0 && ok) {
                size_t base = (size_t)N * 64 + (size_t)rr * 3;
                z_out[base + 0] = p0 + __ldg(lhb + 0);
                z_out[base + 1] = p1 + __ldg(lhb + 1);
                z_out[base + 2] = p2 + __ldg(lhb + 2);
            }
        }
    }
}

// ---------------------------------------------------------------------------
// mlp1T: [N,64] @ [64,128] + bias -> LN(128) -> ReLU   fp16-split m16n8k16
// 256 thr / 8 warps; tile 128 x 128; B frags pre-packed (mat index 4..6)
// ---------------------------------------------------------------------------
#define MLP1T_U32 (2 * 128 * 36 + 2 * 4096 + 384)
#define MLP1T_SMEM (MLP1T_U32 * 4)
__global__ __launch_bounds__(256) void k_mlp1T(
    const float* __restrict__ A, int mat,
    const float* __restrict__ bias, const float* __restrict__ lg,
    const float* __restrict__ lb, float* __restrict__ out, int N) {
    extern __shared__ u32 smu[];
    u32*   Ah = smu;                        // 128*36
    u32*   Al = Ah + 128 * 36;
    uint2* Bh = (uint2*)(Al + 128 * 36);    // 2048 uint2
    uint2* Bl = Bh + 2048;
    float* bs = (float*)(Bl + 2048);        // 128
    float* gs = bs + 128;
    float* bb = gs + 128;
    int tid = threadIdx.x;
    int r0 = blockIdx.x * 128;
    {
        const float4* a4 = (const float4*)A;
        #pragma unroll
        for (int i = 0; i < 8; i++) {
            int idx = tid + i * 256;                // 128 rows x 16 f4
            int row = idx >> 4, c = idx & 15;
            int grow = min(r0 + row, N - 1);
            float4 v = __ldg(&a4[(size_t)grow * 16 + c]);
            u32 h0, l0, h1, l1;
            hsplit(v.x, v.y, h0, l0);
            hsplit(v.z, v.w, h1, l1);
            *(uint2*)&Ah[row * 36 + 2 * c] = make_uint2(h0, h1);
            *(uint2*)&Al[row * 36 + 2 * c] = make_uint2(l0, l1);
        }
        const uint4* ph = (const uint4*)g_bph[mat];
        const uint4* pl = (const uint4*)g_bpl[mat];
        uint4* dh = (uint4*)Bh;
        uint4* dl = (uint4*)Bl;
        #pragma unroll
        for (int i = 0; i < 4; i++) {
            dh[tid + i * 256] = __ldg(&ph[tid + i * 256]);
            dl[tid + i * 256] = __ldg(&pl[tid + i * 256]);
        }
        if (tid < 128) { bs[tid] = bias[tid]; gs[tid] = lg[tid]; bb[tid] = lb[tid]; }
    }
    __syncthreads();
    int warp = tid >> 5, lane = tid & 31;
    int g = lane >> 2, t = lane & 3;
    int wm = warp * 16;
    float acc[16][4];
    #pragma unroll
    for (int nf = 0; nf < 16; nf++)
        #pragma unroll
        for (int c = 0; c < 4; c++) acc[nf][c] = 0.f;
    int b0 = (wm + g) * 36, b1 = (wm + 8 + g) * 36;
    #pragma unroll
    for (int ks = 0; ks < 4; ks++) {
        int kp = ks * 8 + t;
        u32 ah[4], al[4];
        ah[0] = Ah[b0 + kp];     ah[1] = Ah[b1 + kp];
        ah[2] = Ah[b0 + kp + 4]; ah[3] = Ah[b1 + kp + 4];
        al[0] = Al[b0 + kp];     al[1] = Al[b1 + kp];
        al[2] = Al[b0 + kp + 4]; al[3] = Al[b1 + kp + 4];
        #pragma unroll
        for (int nf = 0; nf < 16; nf++) {
            uint2 bh = Bh[(ks * 16 + nf) * 32 + lane];
            uint2 bl = Bl[(ks * 16 + nf) * 32 + lane];
            mmah(acc[nf], ah, bl.x, bl.y);
            mmah(acc[nf], al, bh.x, bh.y);
            mmah(acc[nf], ah, bh.x, bh.y);
        }
    }
    #pragma unroll
    for (int rs = 0; rs < 2; rs++) {
        int rr = r0 + wm + g + rs * 8;
        float y[32];
        #pragma unroll
        for (int nf = 0; nf < 16; nf++) {
            float2 bv = *(float2*)&bs[8 * nf + 2 * t];
            y[2 * nf]     = acc[nf][rs * 2]     + bv.x;
            y[2 * nf + 1] = acc[nf][rs * 2 + 1] + bv.y;
        }
        float s = 0.f, q = 0.f;
        #pragma unroll
        for (int c = 0; c < 32; c++) { s += y[c]; q = fmaf(y[c], y[c], q); }
        s += __shfl_xor_sync(0xffffffffu, s, 1);
        q += __shfl_xor_sync(0xffffffffu, q, 1);
        s += __shfl_xor_sync(0xffffffffu, s, 2);
        q += __shfl_xor_sync(0xffffffffu, q, 2);
        float mu = s * (1.f / 128.f);
        float var = q * (1.f / 128.f) - mu * mu;
        float rsv = rsqrtf(var + 1e-5f);
        if (rr < N) {
            #pragma unroll
            for (int nf = 0; nf < 16; nf++) {
                float2 gv = *(float2*)&gs[8 * nf + 2 * t];
                float2 cv = *(float2*)&bb[8 * nf + 2 * t];
                float2 v;
                v.x = fmaxf((y[2 * nf]     - mu) * rsv * gv.x + cv.x, 0.f);
                v.y = fmaxf((y[2 * nf + 1] - mu) * rsv * gv.y + cv.y, 0.f);
                ((float2*)out)[(size_t)rr * 64 + 4 * nf + t] = v;
            }
        }
    }
}

// ---------------------------------------------------------------------------
// Host launch
// ---------------------------------------------------------------------------
extern "C" void kernel_launch(void* const* d_in, const int* in_sizes, int n_in,
                              void* d_out, int out_size) {
    const float* x    = (const float*)d_in[0];
    const void*  ei   = d_in[1];
    const float* encW = (const float*)d_in[2];
    const float* encB = (const float*)d_in[3];
    const float* t    = (const float*)d_in[4];
    const float* W1   = (const float*)d_in[5];
    const float* b1   = (const float*)d_in[6];
    const float* g1   = (const float*)d_in[7];
    const float* bb1  = (const float*)d_in[8];
    const float* W2   = (const float*)d_in[9];
    const float* b2   = (const float*)d_in[10];
    const float* ng   = (const float*)d_in[11];
    const float* nb   = (const float*)d_in[12];
    const float* lw   = (const float*)d_in[13];
    const float* lb   = (const float*)d_in[14];
    int N = in_sizes[0] / 128;
    int E = in_sizes[1] / 2;
    if (N > NMAX) N = NMAX;
    if (E > EMAX) E = EMAX;
    float* out = (float*)d_out;

    cudaFuncSetAttribute(k_mlp1T, cudaFuncAttributeMaxDynamicSharedMemorySize, MLP1T_SMEM);
    cudaFuncSetAttribute(k_gemmT, cudaFuncAttributeMaxDynamicSharedMemorySize, GEMMT_SMEM);

    float *gh, *gsv, *ghid;
    int *gdeg;
    cudaGetSymbolAddress((void**)&gh,   g_h);
    cudaGetSymbolAddress((void**)&gsv,  g_s);
    cudaGetSymbolAddress((void**)&ghid, g_hid);
    cudaGetSymbolAddress((void**)&gdeg, g_deg);

    int eb4     = (E + 1023) / 1024;
    int aggrB   = (N + 15) / 16;      // 16 threads per row, 256-thread blocks
    int tilesB  = (N + 127) / 128;
    int sblocks = (N + 1023) / 1024;

    // edge preprocessing (CSR by dst)
    cudaMemsetAsync(gdeg, 0, (size_t)N * sizeof(int));
    k_normcount<<<eb4, 256>>>(ei, E);
    // one-time weight fragment packing (overlaps with scan/scatter)
    k_pack<<<7, 256>>>(encW, W1, W2);
    k_scan<<<sblocks, 1024>>>(N);
    k_scatter<<<eb4, 256>>>(E);

    // encoder: x @ encW + encB -> zh (mode 0, mat 0)
    k_gemmT<<<tilesB, 256, GEMMT_SMEM>>>(x, 0, encB, nullptr, nullptr,
                                         nullptr, nullptr, gh, nullptr, N, 0, 0);

    for (int i = 0; i < 3; i++) {
        k_aggr<<<aggrB, 256>>>(t, i, gsv, N);
        k_mlp1T<<<tilesB, 256, MLP1T_SMEM>>>(gsv, 4 + i, b1 + i * 128,
                                             g1 + i * 128, bb1 + i * 128, ghid, N);
        if (i < 2) {
            // mlp2 (+res if i>0) -> gh fp32; zh = relu(LN(gh, ng[i+1]))
            k_gemmT<<<tilesB, 256, GEMMT_SMEM>>>(ghid, 1 + i, b2 + i * 64,
                                                 ng + (i + 1) * 64, nb + (i + 1) * 64,
                                                 nullptr, nullptr, gh, nullptr,
                                                 N, i ? 1 : 0, 1);
        } else {
            // last: res + final LN(ng[0]) + ReLU -> out, head -> out tail
            k_gemmT<<<tilesB, 256, GEMMT_SMEM>>>(ghid, 1 + i, b2 + i * 64,
                                                 ng, nb, lw, lb, gh, out, N, 1, 2);
        }
    }
}

// round 16
// speedup vs baseline: 1.7657x; 1.1508x over previous
#include <cuda_runtime.h>
#include <cuda_fp16.h>

// ---------------------------------------------------------------------------
// DeeperGCN round 16 (round-15 resubmit after infra failure):
//  - k_mlp: phase1 (64->128 MMA + LN + ReLU) hands off to phase2 (128->64 MMA
//    + residual + LN/head) ENTIRELY IN REGISTERS (index algebra: epilogue1
//    ownership == phase2 A-fragment needs). Kills ghid 51MB/layer + 1 launch.
//  - r12 warp-per-row aggr, pre-packed weight frags, fused preprocessing
// ---------------------------------------------------------------------------

#define NMAX 50048
#define EMAX 800000
typedef unsigned long long u64;
typedef unsigned int u32;

__device__ int2     g_edge[EMAX];
__device__ int      g_ssrc[EMAX];
__device__ int      g_deg[NMAX];
__device__ int      g_off[NMAX];
__device__ int      g_cur[NMAX];
__device__ int      g_part[64];
__device__ int      g_scan_done;
__device__ unsigned g_zh [NMAX * 32];     // half2 per entry (64 feats / row)
__device__ float    g_h  [NMAX * 64];
__device__ float    g_s  [NMAX * 64];
// pre-packed weight fragments: mats 0=enc, 1..3=W2_i (gemm type), 4..6=W1_i (mlp)
__device__ uint2    g_bph[7][2048];
__device__ uint2    g_bpl[7][2048];

__device__ __forceinline__ float ex2f(float x) {
    float r; asm("ex2.approx.f32 %0, %1;" : "=f"(r) : "f"(x)); return r;
}
__device__ __forceinline__ unsigned h2pack(float a, float b) {
    __half2 h = __floats2half2_rn(a, b);
    return *(unsigned*)&h;
}
__device__ __forceinline__ float2 h2unpack(unsigned u) {
    __half2 h = *(__half2*)&u;
    return __half22float2(h);
}
__device__ __forceinline__ void hsplit(float a, float b, u32 &hi, u32 &lo) {
    hi = h2pack(a, b);
    float2 f = h2unpack(hi);
    lo = h2pack(a - f.x, b - f.y);
}
__device__ __forceinline__ void mmah(float* d, const u32* a, u32 b0, u32 b1) {
    asm volatile(
        "mma.sync.aligned.m16n8k16.row.col.f32.f16.f16.f32 "
        "{%0,%1,%2,%3}, {%4,%5,%6,%7}, {%8,%9}, {%0,%1,%2,%3};"
        : "+f"(d[0]), "+f"(d[1]), "+f"(d[2]), "+f"(d[3])
        : "r"(a[0]), "r"(a[1]), "r"(a[2]), "r"(a[3]), "r"(b0), "r"(b1));
}

// ---------------------------------------------------------------------------
// k_pack: one-time fragment packing of all 7 weight matrices (32KB each)
// ---------------------------------------------------------------------------
__global__ __launch_bounds__(256) void k_pack(const float* __restrict__ encW,
                                              const float* __restrict__ W1,
                                              const float* __restrict__ W2) {
    __shared__ float sw[8192];
    int b = blockIdx.x;  // 0: enc, 1..3: W2_i, 4..6: W1_i
    const float* src = (b == 0) ? encW : (b < 4 ? W2 + (b - 1) * 8192
                                                : W1 + (b - 4) * 8192);
    int tid = threadIdx.x;
    const float4* s4 = (const float4*)src;
    #pragma unroll
    for (int i = 0; i < 8; i++)
        ((float4*)sw)[tid + i * 256] = __ldg(&s4[tid + i * 256]);
    __syncthreads();
    bool mlp = (b >= 4);
    #pragma unroll
    for (int i = 0; i < 8; i++) {
        int id = tid + i * 256;                 // 0..2047
        int ln = id & 31;
        int g = ln >> 2, t = ln & 3;
        int nf, ks, stride;
        if (!mlp) { nf = (id >> 5) & 7;  ks = id >> 8; stride = 64; }
        else      { nf = (id >> 5) & 15; ks = id >> 9; stride = 128; }
        int n = nf * 8 + g, k0 = ks * 16 + 2 * t;
        float w00 = sw[(k0)     * stride + n];
        float w01 = sw[(k0 + 1) * stride + n];
        float w10 = sw[(k0 + 8) * stride + n];
        float w11 = sw[(k0 + 9) * stride + n];
        u32 bh0, bl0, bh1, bl1;
        hsplit(w00, w01, bh0, bl0);
        hsplit(w10, w11, bh1, bl1);
        g_bph[b][id] = make_uint2(bh0, bh1);
        g_bpl[b][id] = make_uint2(bl0, bl1);
    }
}

// ---------------------------------------------------------------------------
// Edge preprocessing (r12, unchanged)
// ---------------------------------------------------------------------------
__global__ void k_normcount(const void* __restrict__ raw, int E) {
    __shared__ int s_is64;
    int tid = threadIdx.x;
    if (tid < 32) {
        const int* w = (const int*)raw;
        int bad = 0;
        int lim = min(128, E);
        for (int i = tid; i < lim; i += 32) bad |= w[2 * i + 1];
        unsigned b = __ballot_sync(0xffffffffu, bad != 0);
        if (tid == 0) s_is64 = (b == 0) ? 1 : 0;
    }
    if (blockIdx.x == 0 && tid == 0) g_scan_done = 0;
    __syncthreads();
    int is64 = s_is64;
    int base = (blockIdx.x * blockDim.x + tid) * 4;
    if (base >= E) return;
    if (is64) {
        const long long* p = (const long long*)raw;
        #pragma unroll
        for (int j = 0; j < 4; j++) {
            int e = base + j;
            if (e < E) {
                int s = (int)p[e], d = (int)p[(size_t)E + e];
                g_edge[e] = make_int2(s, d);
                atomicAdd(&g_deg[d], 1);
            }
        }
    } else {
        const int* p = (const int*)raw;
        #pragma unroll
        for (int j = 0; j < 4; j++) {
            int e = base + j;
            if (e < E) {
                int s = p[e], d = p[(size_t)E + e];
                g_edge[e] = make_int2(s, d);
                atomicAdd(&g_deg[d], 1);
            }
        }
    }
}

__global__ void k_scan(int n) {
    __shared__ int wsum[32];
    __shared__ int amLast;
    __shared__ int pp[64];
    int tid = threadIdx.x;
    int i = blockIdx.x * 1024 + tid;
    int v = (i < n) ? g_deg[i] : 0;
    int lane = tid & 31, wid = tid >> 5;
    int s = v;
    #pragma unroll
    for (int o = 1; o < 32; o <<= 1) {
        int t = __shfl_up_sync(0xffffffffu, s, o);
        if (lane >= o) s += t;
    }
    if (lane == 31) wsum[wid] = s;
    __syncthreads();
    if (wid == 0) {
        int w = wsum[lane];
        #pragma unroll
        for (int o = 1; o < 32; o <<= 1) {
            int t = __shfl_up_sync(0xffffffffu, w, o);
            if (lane >= o) w += t;
        }
        wsum[lane] = w;
    }
    __syncthreads();
    int base = wid ? wsum[wid - 1] : 0;
    int excl = base + s - v;
    if (i < n) { g_off[i] = excl; g_cur[i] = excl; }
    if (tid == 1023) {
        g_part[blockIdx.x] = base + s;
        __threadfence();
        int t = atomicAdd(&g_scan_done, 1);
        amLast = (t == (int)gridDim.x - 1);
    }
    __syncthreads();
    if (amLast) {
        int P = gridDim.x;
        if (tid < 64) pp[tid] = (tid < P) ? g_part[tid] : 0;
        __syncthreads();
        if (tid == 0) {
            int acc = 0;
            for (int k = 0; k < P; k++) { int vv = pp[k]; pp[k] = acc; acc += vv; }
        }
        __syncthreads();
        if (tid < P) g_part[tid] = pp[tid];
    }
}

__global__ void k_scatter(int E) {
    int base = (blockIdx.x * blockDim.x + threadIdx.x) * 4;
    if (base >= E) return;
    #pragma unroll
    for (int j = 0; j < 4; j++) {
        int e = base + j;
        if (e < E) {
            int2 ed = g_edge[e];
            int pos = atomicAdd(&g_cur[ed.y], 1) + g_part[ed.y >> 10];
            g_ssrc[pos] = ed.x;
        }
    }
}

// ---------------------------------------------------------------------------
// Softmax aggregation, warp per destination node (r12, best-known)
// ---------------------------------------------------------------------------
__global__ void k_aggr(const float* __restrict__ tp, int li,
                       float* __restrict__ so, int N) {
    int w = (blockIdx.x * blockDim.x + threadIdx.x) >> 5;
    int lane = threadIdx.x & 31;
    if (w >= N) return;
    float tl = __ldg(tp + li) * 1.4426950408889634f;
    int beg = g_off[w] + g_part[w >> 10];
    int dg = g_deg[w];
    float se0 = 0.f, se1 = 0.f, sn0 = 0.f, sn1 = 0.f;
    #pragma unroll 4
    for (int j = 0; j < dg; j++) {
        int s = __ldg(&g_ssrc[beg + j]);
        float2 v = h2unpack(__ldg(&g_zh[(size_t)s * 32 + lane]));
        float m0 = fmaxf(v.x, 0.f);
        float m1 = fmaxf(v.y, 0.f);
        float e0 = ex2f(m0 * tl);
        float e1 = ex2f(m1 * tl);
        se0 += e0; se1 += e1;
        sn0 = fmaf(m0, e0, sn0);
        sn1 = fmaf(m1, e1, sn1);
    }
    float2 zd = h2unpack(g_zh[(size_t)w * 32 + lane]);
    float2 o;
    o.x = zd.x + fmaf(1e-7f, se0, sn0) / (se0 + 1e-16f);
    o.y = zd.y + fmaf(1e-7f, se1, sn1) / (se1 + 1e-16f);
    ((float2*)so)[(size_t)w * 32 + lane] = o;
}

// ---------------------------------------------------------------------------
// gemmT: encoder only ([N,128] @ [128,64] + bias -> zh)
// ---------------------------------------------------------------------------
#define GEMMT_U32 (2 * 128 * 68 + 2 * 4096 + 400)
#define GEMMT_SMEM (GEMMT_U32 * 4)
__global__ __launch_bounds__(256) void k_gemmT(
    const float* __restrict__ A, int mat,
    const float* __restrict__ bias, int N) {
    extern __shared__ u32 smu[];
    u32*   Ah  = smu;                       // 128*68
    u32*   Al  = Ah + 128 * 68;             // 128*68
    uint2* Bh  = (uint2*)(Al + 128 * 68);   // 2048 uint2
    uint2* Bl  = Bh + 2048;                 // 2048 uint2
    float* bs  = (float*)(Bl + 2048);       // 64
    int tid = threadIdx.x;
    int r0 = blockIdx.x * 128;
    {
        const float4* a4 = (const float4*)A;
        #pragma unroll
        for (int i = 0; i < 16; i++) {
            int idx = tid + i * 256;                // 128 rows x 32 f4
            int row = idx >> 5, c = idx & 31;
            int grow = min(r0 + row, N - 1);
            float4 v = __ldg(&a4[(size_t)grow * 32 + c]);
            u32 h0, l0, h1, l1;
            hsplit(v.x, v.y, h0, l0);
            hsplit(v.z, v.w, h1, l1);
            *(uint2*)&Ah[row * 68 + 2 * c] = make_uint2(h0, h1);
            *(uint2*)&Al[row * 68 + 2 * c] = make_uint2(l0, l1);
        }
        const uint4* ph = (const uint4*)g_bph[mat];
        const uint4* pl = (const uint4*)g_bpl[mat];
        uint4* dh = (uint4*)Bh;
        uint4* dl = (uint4*)Bl;
        #pragma unroll
        for (int i = 0; i < 4; i++) {
            dh[tid + i * 256] = __ldg(&ph[tid + i * 256]);
            dl[tid + i * 256] = __ldg(&pl[tid + i * 256]);
        }
        if (tid < 64) bs[tid] = bias[tid];
    }
    __syncthreads();
    int warp = tid >> 5, lane = tid & 31;
    int g = lane >> 2, t = lane & 3;
    int wm = warp * 16;
    float acc[8][4];
    #pragma unroll
    for (int nf = 0; nf < 8; nf++)
        #pragma unroll
        for (int c = 0; c < 4; c++) acc[nf][c] = 0.f;
    int b0 = (wm + g) * 68, b1 = (wm + 8 + g) * 68;
    #pragma unroll
    for (int ks = 0; ks < 8; ks++) {
        int kp = ks * 8 + t;
        u32 ah[4], al[4];
        ah[0] = Ah[b0 + kp];     ah[1] = Ah[b1 + kp];
        ah[2] = Ah[b0 + kp + 4]; ah[3] = Ah[b1 + kp + 4];
        al[0] = Al[b0 + kp];     al[1] = Al[b1 + kp];
        al[2] = Al[b0 + kp + 4]; al[3] = Al[b1 + kp + 4];
        #pragma unroll
        for (int nf = 0; nf < 8; nf++) {
            uint2 bh = Bh[(ks * 8 + nf) * 32 + lane];
            uint2 bl = Bl[(ks * 8 + nf) * 32 + lane];
            mmah(acc[nf], ah, bl.x, bl.y);
            mmah(acc[nf], al, bh.x, bh.y);
            mmah(acc[nf], ah, bh.x, bh.y);
        }
    }
    #pragma unroll
    for (int rs = 0; rs < 2; rs++) {
        int rr = r0 + wm + g + rs * 8;
        if (rr >= N) continue;
        #pragma unroll
        for (int nf = 0; nf < 8; nf++) {
            float2 bv = *(float2*)&bs[8 * nf + 2 * t];
            float y0 = acc[nf][rs * 2]     + bv.x;
            float y1 = acc[nf][rs * 2 + 1] + bv.y;
            g_zh[(size_t)rr * 32 + 4 * nf + t] = h2pack(y0, y1);
        }
    }
}

// ---------------------------------------------------------------------------
// k_mlp: FUSED mlp1 + mlp2 with register fragment handoff.
// Phase1: A(g_s)[128,64] @ W1[64,128] + b1 -> LN(128) -> ReLU -> hsplit into
//         phase2 A-frag registers (ownership identity: colpair 4nf+t == kp set)
// Phase2: @ W2[128,64] + b2 (+res) -> mode1: gh + zh=relu(LN); mode2: out+head
// 256 thr / 8 warps, 128-row tiles, 2 CTA/SM.
// ---------------------------------------------------------------------------
#define MLP_U32 (2 * 128 * 36 + 4 * 4096 + 384 + 192 + 208)
#define MLP_SMEM (MLP_U32 * 4)
__global__ __launch_bounds__(256, 2) void k_mlp(
    const float* __restrict__ A, int mat1, int mat2,
    const float* __restrict__ b1p, const float* __restrict__ g1p,
    const float* __restrict__ c1p, const float* __restrict__ b2p,
    const float* __restrict__ g2p, const float* __restrict__ c2p,
    const float* __restrict__ lw, const float* __restrict__ lhb,
    float* __restrict__ h_out, float* __restrict__ z_out,
    int N, int addres, int mode) {
    extern __shared__ u32 smu[];
    u32*   Ah  = smu;                        // 128*36
    u32*   Al  = Ah + 128 * 36;
    uint2* B1h = (uint2*)(Al + 128 * 36);    // 2048 uint2
    uint2* B1l = B1h + 2048;
    uint2* B2h = B1l + 2048;
    uint2* B2l = B2h + 2048;
    float* bs1 = (float*)(B2l + 2048);       // 128
    float* gs1 = bs1 + 128;
    float* cs1 = gs1 + 128;
    float* bs2 = cs1 + 128;                  // 64
    float* gs2 = bs2 + 64;
    float* cs2 = gs2 + 64;
    float* lws = cs2 + 64;                   // 208
    int tid = threadIdx.x;
    int r0 = blockIdx.x * 128;
    // stage A1 (g_s fp32 -> hi/lo frags), B1, B2, params
    {
        const float4* a4 = (const float4*)A;
        #pragma unroll
        for (int i = 0; i < 8; i++) {
            int idx = tid + i * 256;                // 128 rows x 16 f4
            int row = idx >> 4, c = idx & 15;
            int grow = min(r0 + row, N - 1);
            float4 v = __ldg(&a4[(size_t)grow * 16 + c]);
            u32 h0, l0, h1, l1;
            hsplit(v.x, v.y, h0, l0);
            hsplit(v.z, v.w, h1, l1);
            *(uint2*)&Ah[row * 36 + 2 * c] = make_uint2(h0, h1);
            *(uint2*)&Al[row * 36 + 2 * c] = make_uint2(l0, l1);
        }
        const uint4* p1h = (const uint4*)g_bph[mat1];
        const uint4* p1l = (const uint4*)g_bpl[mat1];
        const uint4* p2h = (const uint4*)g_bph[mat2];
        const uint4* p2l = (const uint4*)g_bpl[mat2];
        #pragma unroll
        for (int i = 0; i < 4; i++) {
            ((uint4*)B1h)[tid + i * 256] = __ldg(&p1h[tid + i * 256]);
            ((uint4*)B1l)[tid + i * 256] = __ldg(&p1l[tid + i * 256]);
            ((uint4*)B2h)[tid + i * 256] = __ldg(&p2h[tid + i * 256]);
            ((uint4*)B2l)[tid + i * 256] = __ldg(&p2l[tid + i * 256]);
        }
        if (tid < 128) { bs1[tid] = b1p[tid]; gs1[tid] = g1p[tid]; cs1[tid] = c1p[tid]; }
        else if (tid < 192) {
            int k = tid - 128;
            bs2[k] = b2p[k];
            if (mode) { gs2[k] = g2p[k]; cs2[k] = c2p[k]; }
        }
        if (mode == 2 && tid >= 192 && tid < 240)
            ((float4*)lws)[tid - 192] = ((const float4*)lw)[tid - 192];
    }
    __syncthreads();
    int warp = tid >> 5, lane = tid & 31;
    int lg = lane >> 2, t = lane & 3;
    int wm = warp * 16;
    // ---- Phase 1: [128,64]@[64,128] ----
    float acc1[16][4];
    #pragma unroll
    for (int nf = 0; nf < 16; nf++)
        #pragma unroll
        for (int c = 0; c < 4; c++) acc1[nf][c] = 0.f;
    {
        int b0 = (wm + lg) * 36, b1 = (wm + 8 + lg) * 36;
        #pragma unroll
        for (int ks = 0; ks < 4; ks++) {
            int kp = ks * 8 + t;
            u32 ah[4], al[4];
            ah[0] = Ah[b0 + kp];     ah[1] = Ah[b1 + kp];
            ah[2] = Ah[b0 + kp + 4]; ah[3] = Ah[b1 + kp + 4];
            al[0] = Al[b0 + kp];     al[1] = Al[b1 + kp];
            al[2] = Al[b0 + kp + 4]; al[3] = Al[b1 + kp + 4];
            #pragma unroll
            for (int nf = 0; nf < 16; nf++) {
                uint2 bh = B1h[(ks * 16 + nf) * 32 + lane];
                uint2 bl = B1l[(ks * 16 + nf) * 32 + lane];
                mmah(acc1[nf], ah, bl.x, bl.y);
                mmah(acc1[nf], al, bh.x, bh.y);
                mmah(acc1[nf], ah, bh.x, bh.y);
            }
        }
    }
    // ---- Epilogue 1 -> phase2 A-fragment registers ----
    u32 fh[2][16], fl[2][16];
    #pragma unroll
    for (int rs = 0; rs < 2; rs++) {
        float y[32];
        #pragma unroll
        for (int nf = 0; nf < 16; nf++) {
            float2 bv = *(float2*)&bs1[8 * nf + 2 * t];
            y[2 * nf]     = acc1[nf][rs * 2]     + bv.x;
            y[2 * nf + 1] = acc1[nf][rs * 2 + 1] + bv.y;
        }
        float s = 0.f, q = 0.f;
        #pragma unroll
        for (int c = 0; c < 32; c++) { s += y[c]; q = fmaf(y[c], y[c], q); }
        s += __shfl_xor_sync(0xffffffffu, s, 1);
        q += __shfl_xor_sync(0xffffffffu, q, 1);
        s += __shfl_xor_sync(0xffffffffu, s, 2);
        q += __shfl_xor_sync(0xffffffffu, q, 2);
        float mu = s * (1.f / 128.f);
        float var = q * (1.f / 128.f) - mu * mu;
        float rsv = rsqrtf(var + 1e-5f);
        #pragma unroll
        for (int nf = 0; nf < 16; nf++) {
            float2 gv = *(float2*)&gs1[8 * nf + 2 * t];
            float2 cv = *(float2*)&cs1[8 * nf + 2 * t];
            float o0 = fmaxf((y[2 * nf]     - mu) * rsv * gv.x + cv.x, 0.f);
            float o1 = fmaxf((y[2 * nf + 1] - mu) * rsv * gv.y + cv.y, 0.f);
            hsplit(o0, o1, fh[rs][nf], fl[rs][nf]);
        }
    }
    // ---- Phase 2: [128,128]@[128,64], A-frags from registers ----
    float acc2[8][4];
    #pragma unroll
    for (int nf = 0; nf < 8; nf++)
        #pragma unroll
        for (int c = 0; c < 4; c++) acc2[nf][c] = 0.f;
    #pragma unroll
    for (int ks = 0; ks < 8; ks++) {
        u32 ah[4], al[4];
        ah[0] = fh[0][2 * ks];     ah[1] = fh[1][2 * ks];
        ah[2] = fh[0][2 * ks + 1]; ah[3] = fh[1][2 * ks + 1];
        al[0] = fl[0][2 * ks];     al[1] = fl[1][2 * ks];
        al[2] = fl[0][2 * ks + 1]; al[3] = fl[1][2 * ks + 1];
        #pragma unroll
        for (int nf = 0; nf < 8; nf++) {
            uint2 bh = B2h[(ks * 8 + nf) * 32 + lane];
            uint2 bl = B2l[(ks * 8 + nf) * 32 + lane];
            mmah(acc2[nf], ah, bl.x, bl.y);
            mmah(acc2[nf], al, bh.x, bh.y);
            mmah(acc2[nf], ah, bh.x, bh.y);
        }
    }
    // ---- Epilogue 2 (as gemmT modes 1/2) ----
    #pragma unroll
    for (int rs = 0; rs < 2; rs++) {
        int rr = r0 + wm + lg + rs * 8;
        bool ok = rr < N;
        float y[16];
        #pragma unroll
        for (int nf = 0; nf < 8; nf++) {
            float2 bv = *(float2*)&bs2[8 * nf + 2 * t];
            y[2 * nf]     = acc2[nf][rs * 2]     + bv.x;
            y[2 * nf + 1] = acc2[nf][rs * 2 + 1] + bv.y;
        }
        if (addres && ok) {
            #pragma unroll
            for (int nf = 0; nf < 8; nf++) {
                float2 h = ((const float2*)h_out)[(size_t)rr * 32 + 4 * nf + t];
                y[2 * nf] += h.x; y[2 * nf + 1] += h.y;
            }
        }
        if (mode == 1 && ok) {
            #pragma unroll
            for (int nf = 0; nf < 8; nf++) {
                float2 v; v.x = y[2 * nf]; v.y = y[2 * nf + 1];
                ((float2*)h_out)[(size_t)rr * 32 + 4 * nf + t] = v;
            }
        }
        float s = 0.f, q = 0.f;
        #pragma unroll
        for (int c = 0; c < 16; c++) { s += y[c]; q = fmaf(y[c], y[c], q); }
        s += __shfl_xor_sync(0xffffffffu, s, 1);
        q += __shfl_xor_sync(0xffffffffu, q, 1);
        s += __shfl_xor_sync(0xffffffffu, s, 2);
        q += __shfl_xor_sync(0xffffffffu, q, 2);
        float mu = s * (1.f / 64.f);
        float var = q * (1.f / 64.f) - mu * mu;
        float rsv = rsqrtf(var + 1e-5f);
        float o16[16];
        #pragma unroll
        for (int nf = 0; nf < 8; nf++) {
            float2 gv = *(float2*)&gs2[8 * nf + 2 * t];
            float2 cv = *(float2*)&cs2[8 * nf + 2 * t];
            o16[2 * nf]     = fmaxf((y[2 * nf]     - mu) * rsv * gv.x + cv.x, 0.f);
            o16[2 * nf + 1] = fmaxf((y[2 * nf + 1] - mu) * rsv * gv.y + cv.y, 0.f);
        }
        if (mode == 1) {
            if (ok) {
                #pragma unroll
                for (int nf = 0; nf < 8; nf++)
                    g_zh[(size_t)rr * 32 + 4 * nf + t] = h2pack(o16[2 * nf], o16[2 * nf + 1]);
            }
        } else {  // mode 2: final out + head
            if (ok) {
                #pragma unroll
                for (int nf = 0; nf < 8; nf++) {
                    float2 v; v.x = o16[2 * nf]; v.y = o16[2 * nf + 1];
                    ((float2*)z_out)[(size_t)rr * 32 + 4 * nf + t] = v;
                }
            }
            float p0 = 0.f, p1 = 0.f, p2 = 0.f;
            #pragma unroll
            for (int nf = 0; nf < 8; nf++) {
                int c0 = 8 * nf + 2 * t, c1 = c0 + 1;
                p0 = fmaf(o16[2 * nf], lws[c0 * 3 + 0], p0);
                p1 = fmaf(o16[2 * nf], lws[c0 * 3 + 1], p1);
                p2 = fmaf(o16[2 * nf], lws[c0 * 3 + 2], p2);
                p0 = fmaf(o16[2 * nf + 1], lws[c1 * 3 + 0], p0);
                p1 = fmaf(o16[2 * nf + 1], lws[c1 * 3 + 1], p1);
                p2 = fmaf(o16[2 * nf + 1], lws[c1 * 3 + 2], p2);
            }
            p0 += __shfl_xor_sync(0xffffffffu, p0, 1);
            p1 += __shfl_xor_sync(0xffffffffu, p1, 1);
            p2 += __shfl_xor_sync(0xffffffffu, p2, 1);
            p0 += __shfl_xor_sync(0xffffffffu, p0, 2);
            p1 += __shfl_xor_sync(0xffffffffu, p1, 2);
            p2 += __shfl_xor_sync(0xffffffffu, p2, 2);
            if (t == 0 && ok) {
                size_t base = (size_t)N * 64 + (size_t)rr * 3;
                z_out[base + 0] = p0 + __ldg(lhb + 0);
                z_out[base + 1] = p1 + __ldg(lhb + 1);
                z_out[base + 2] = p2 + __ldg(lhb + 2);
            }
        }
    }
}

// ---------------------------------------------------------------------------
// Host launch
// ---------------------------------------------------------------------------
extern "C" void kernel_launch(void* const* d_in, const int* in_sizes, int n_in,
                              void* d_out, int out_size) {
    const float* x    = (const float*)d_in[0];
    const void*  ei   = d_in[1];
    const float* encW = (const float*)d_in[2];
    const float* encB = (const float*)d_in[3];
    const float* t    = (const float*)d_in[4];
    const float* W1   = (const float*)d_in[5];
    const float* b1   = (const float*)d_in[6];
    const float* g1   = (const float*)d_in[7];
    const float* bb1  = (const float*)d_in[8];
    const float* W2   = (const float*)d_in[9];
    const float* b2   = (const float*)d_in[10];
    const float* ng   = (const float*)d_in[11];
    const float* nb   = (const float*)d_in[12];
    const float* lw   = (const float*)d_in[13];
    const float* lb   = (const float*)d_in[14];
    int N = in_sizes[0] / 128;
    int E = in_sizes[1] / 2;
    if (N > NMAX) N = NMAX;
    if (E > EMAX) E = EMAX;
    float* out = (float*)d_out;

    cudaFuncSetAttribute(k_mlp,   cudaFuncAttributeMaxDynamicSharedMemorySize, MLP_SMEM);
    cudaFuncSetAttribute(k_gemmT, cudaFuncAttributeMaxDynamicSharedMemorySize, GEMMT_SMEM);

    float *gh, *gsv;
    int *gdeg;
    cudaGetSymbolAddress((void**)&gh,   g_h);
    cudaGetSymbolAddress((void**)&gsv,  g_s);
    cudaGetSymbolAddress((void**)&gdeg, g_deg);

    int eb4     = (E + 1023) / 1024;
    int rowsW   = (N + 7) / 8;
    int tilesB  = (N + 127) / 128;
    int sblocks = (N + 1023) / 1024;

    // edge preprocessing (CSR by dst)
    cudaMemsetAsync(gdeg, 0, (size_t)N * sizeof(int));
    k_normcount<<<eb4, 256>>>(ei, E);
    k_pack<<<7, 256>>>(encW, W1, W2);
    k_scan<<<sblocks, 1024>>>(N);
    k_scatter<<<eb4, 256>>>(E);

    // encoder: x @ encW + encB -> zh (mat 0)
    k_gemmT<<<tilesB, 256, GEMMT_SMEM>>>(x, 0, encB, N);

    for (int i = 0; i < 3; i++) {
        k_aggr<<<rowsW, 256>>>(t, i, gsv, N);
        if (i < 2) {
            k_mlp<<<tilesB, 256, MLP_SMEM>>>(gsv, 4 + i, 1 + i,
                                             b1 + i * 128, g1 + i * 128, bb1 + i * 128,
                                             b2 + i * 64, ng + (i + 1) * 64, nb + (i + 1) * 64,
                                             nullptr, nullptr, gh, nullptr,
                                             N, i ? 1 : 0, 1);
        } else {
            k_mlp<<<tilesB, 256, MLP_SMEM>>>(gsv, 4 + i, 1 + i,
                                             b1 + i * 128, g1 + i * 128, bb1 + i * 128,
                                             b2 + i * 64, ng, nb,
                                             lw, lb, gh, out, N, 1, 2);
        }
    }
}

// round 17
// speedup vs baseline: 1.7662x; 1.0003x over previous
#include <cuda_runtime.h>
#include <cuda_fp16.h>

// ---------------------------------------------------------------------------
// DeeperGCN round 17: r16 base (best: 217.1us) + two refinements.
//  - k_normpack: weight packing fused into normcount grid (last 7 blocks)
//  - k_aggr: int4-vectorized CSR index loads (4 indep z-chains per group)
//  - fused register-handoff MLP, pre-packed frags, fp16 gather (r16)
// ---------------------------------------------------------------------------

#define NMAX 50048
#define EMAX 800000
typedef unsigned long long u64;
typedef unsigned int u32;

__device__ int2     g_edge[EMAX];
__device__ int      g_ssrc[EMAX];
__device__ int      g_deg[NMAX];
__device__ int      g_off[NMAX];
__device__ int      g_cur[NMAX];
__device__ int      g_part[64];
__device__ int      g_scan_done;
__device__ unsigned g_zh [NMAX * 32];     // half2 per entry (64 feats / row)
__device__ float    g_h  [NMAX * 64];
__device__ float    g_s  [NMAX * 64];
// pre-packed weight fragments: mats 0=enc, 1..3=W2_i (gemm type), 4..6=W1_i (mlp)
__device__ uint2    g_bph[7][2048];
__device__ uint2    g_bpl[7][2048];

__device__ __forceinline__ float ex2f(float x) {
    float r; asm("ex2.approx.f32 %0, %1;" : "=f"(r) : "f"(x)); return r;
}
__device__ __forceinline__ unsigned h2pack(float a, float b) {
    __half2 h = __floats2half2_rn(a, b);
    return *(unsigned*)&h;
}
__device__ __forceinline__ float2 h2unpack(unsigned u) {
    __half2 h = *(__half2*)&u;
    return __half22float2(h);
}
__device__ __forceinline__ void hsplit(float a, float b, u32 &hi, u32 &lo) {
    hi = h2pack(a, b);
    float2 f = h2unpack(hi);
    lo = h2pack(a - f.x, b - f.y);
}
__device__ __forceinline__ void mmah(float* d, const u32* a, u32 b0, u32 b1) {
    asm volatile(
        "mma.sync.aligned.m16n8k16.row.col.f32.f16.f16.f32 "
        "{%0,%1,%2,%3}, {%4,%5,%6,%7}, {%8,%9}, {%0,%1,%2,%3};"
        : "+f"(d[0]), "+f"(d[1]), "+f"(d[2]), "+f"(d[3])
        : "r"(a[0]), "r"(a[1]), "r"(a[2]), "r"(a[3]), "r"(b0), "r"(b1));
}

// ---------------------------------------------------------------------------
// k_normpack: edge normalize+count (blocks [0, eb4)) + weight fragment
// packing (last 7 blocks). Pack work rides behind the atomic-bound count.
// ---------------------------------------------------------------------------
__global__ __launch_bounds__(256) void k_normpack(
    const void* __restrict__ raw, int E,
    const float* __restrict__ encW, const float* __restrict__ W1,
    const float* __restrict__ W2) {
    __shared__ float sw[8192];
    int tid = threadIdx.x;
    int packBase = gridDim.x - 7;
    if (blockIdx.x >= packBase) {
        // ---- pack branch ----
        int b = blockIdx.x - packBase;   // 0: enc, 1..3: W2_i, 4..6: W1_i
        const float* src = (b == 0) ? encW : (b < 4 ? W2 + (b - 1) * 8192
                                                    : W1 + (b - 4) * 8192);
        const float4* s4 = (const float4*)src;
        #pragma unroll
        for (int i = 0; i < 8; i++)
            ((float4*)sw)[tid + i * 256] = __ldg(&s4[tid + i * 256]);
        __syncthreads();
        bool mlp = (b >= 4);
        #pragma unroll
        for (int i = 0; i < 8; i++) {
            int id = tid + i * 256;                 // 0..2047
            int ln = id & 31;
            int g = ln >> 2, t = ln & 3;
            int nf, ks, stride;
            if (!mlp) { nf = (id >> 5) & 7;  ks = id >> 8; stride = 64; }
            else      { nf = (id >> 5) & 15; ks = id >> 9; stride = 128; }
            int n = nf * 8 + g, k0 = ks * 16 + 2 * t;
            float w00 = sw[(k0)     * stride + n];
            float w01 = sw[(k0 + 1) * stride + n];
            float w10 = sw[(k0 + 8) * stride + n];
            float w11 = sw[(k0 + 9) * stride + n];
            u32 bh0, bl0, bh1, bl1;
            hsplit(w00, w01, bh0, bl0);
            hsplit(w10, w11, bh1, bl1);
            g_bph[b][id] = make_uint2(bh0, bh1);
            g_bpl[b][id] = make_uint2(bl0, bl1);
        }
        return;
    }
    // ---- normcount branch ----
    __shared__ int s_is64;
    if (tid < 32) {
        const int* w = (const int*)raw;
        int bad = 0;
        int lim = min(128, E);
        for (int i = tid; i < lim; i += 32) bad |= w[2 * i + 1];
        unsigned b = __ballot_sync(0xffffffffu, bad != 0);
        if (tid == 0) s_is64 = (b == 0) ? 1 : 0;
    }
    if (blockIdx.x == 0 && tid == 0) g_scan_done = 0;
    __syncthreads();
    int is64 = s_is64;
    int base = (blockIdx.x * blockDim.x + tid) * 4;
    if (base >= E) return;
    if (is64) {
        const long long* p = (const long long*)raw;
        #pragma unroll
        for (int j = 0; j < 4; j++) {
            int e = base + j;
            if (e < E) {
                int s = (int)p[e], d = (int)p[(size_t)E + e];
                g_edge[e] = make_int2(s, d);
                atomicAdd(&g_deg[d], 1);
            }
        }
    } else {
        const int* p = (const int*)raw;
        #pragma unroll
        for (int j = 0; j < 4; j++) {
            int e = base + j;
            if (e < E) {
                int s = p[e], d = p[(size_t)E + e];
                g_edge[e] = make_int2(s, d);
                atomicAdd(&g_deg[d], 1);
            }
        }
    }
}

__global__ void k_scan(int n) {
    __shared__ int wsum[32];
    __shared__ int amLast;
    __shared__ int pp[64];
    int tid = threadIdx.x;
    int i = blockIdx.x * 1024 + tid;
    int v = (i < n) ? g_deg[i] : 0;
    int lane = tid & 31, wid = tid >> 5;
    int s = v;
    #pragma unroll
    for (int o = 1; o < 32; o <<= 1) {
        int t = __shfl_up_sync(0xffffffffu, s, o);
        if (lane >= o) s += t;
    }
    if (lane == 31) wsum[wid] = s;
    __syncthreads();
    if (wid == 0) {
        int w = wsum[lane];
        #pragma unroll
        for (int o = 1; o < 32; o <<= 1) {
            int t = __shfl_up_sync(0xffffffffu, w, o);
            if (lane >= o) w += t;
        }
        wsum[lane] = w;
    }
    __syncthreads();
    int base = wid ? wsum[wid - 1] : 0;
    int excl = base + s - v;
    if (i < n) { g_off[i] = excl; g_cur[i] = excl; }
    if (tid == 1023) {
        g_part[blockIdx.x] = base + s;
        __threadfence();
        int t = atomicAdd(&g_scan_done, 1);
        amLast = (t == (int)gridDim.x - 1);
    }
    __syncthreads();
    if (amLast) {
        int P = gridDim.x;
        if (tid < 64) pp[tid] = (tid < P) ? g_part[tid] : 0;
        __syncthreads();
        if (tid == 0) {
            int acc = 0;
            for (int k = 0; k < P; k++) { int vv = pp[k]; pp[k] = acc; acc += vv; }
        }
        __syncthreads();
        if (tid < P) g_part[tid] = pp[tid];
    }
}

__global__ void k_scatter(int E) {
    int base = (blockIdx.x * blockDim.x + threadIdx.x) * 4;
    if (base >= E) return;
    #pragma unroll
    for (int j = 0; j < 4; j++) {
        int e = base + j;
        if (e < E) {
            int2 ed = g_edge[e];
            int pos = atomicAdd(&g_cur[ed.y], 1) + g_part[ed.y >> 10];
            g_ssrc[pos] = ed.x;
        }
    }
}

// ---------------------------------------------------------------------------
// Softmax aggregation, warp per destination node, int4 index vectorization.
// Edge iteration order unchanged -> bit-identical to r16.
// ---------------------------------------------------------------------------
__global__ void k_aggr(const float* __restrict__ tp, int li,
                       float* __restrict__ so, int N) {
    int w = (blockIdx.x * blockDim.x + threadIdx.x) >> 5;
    int lane = threadIdx.x & 31;
    if (w >= N) return;
    float tl = __ldg(tp + li) * 1.4426950408889634f;
    int beg = g_off[w] + g_part[w >> 10];
    int dg = g_deg[w];
    float se0 = 0.f, se1 = 0.f, sn0 = 0.f, sn1 = 0.f;
    #define AGGR_EDGE(S) {                                        \
        float2 v = h2unpack(__ldg(&g_zh[(size_t)(S) * 32 + lane]));\
        float m0 = fmaxf(v.x, 0.f);                               \
        float m1 = fmaxf(v.y, 0.f);                               \
        float e0 = ex2f(m0 * tl);                                 \
        float e1 = ex2f(m1 * tl);                                 \
        se0 += e0; se1 += e1;                                     \
        sn0 = fmaf(m0, e0, sn0);                                  \
        sn1 = fmaf(m1, e1, sn1);                                  \
    }
    int j = 0;
    int pre = (4 - (beg & 3)) & 3;
    if (pre > dg) pre = dg;
    for (; j < pre; j++) {
        int s = __ldg(&g_ssrc[beg + j]);
        AGGR_EDGE(s);
    }
    for (; j + 4 <= dg; j += 4) {
        int4 s4 = __ldg((const int4*)&g_ssrc[beg + j]);
        AGGR_EDGE(s4.x);
        AGGR_EDGE(s4.y);
        AGGR_EDGE(s4.z);
        AGGR_EDGE(s4.w);
    }
    for (; j < dg; j++) {
        int s = __ldg(&g_ssrc[beg + j]);
        AGGR_EDGE(s);
    }
    #undef AGGR_EDGE
    float2 zd = h2unpack(g_zh[(size_t)w * 32 + lane]);
    float2 o;
    o.x = zd.x + fmaf(1e-7f, se0, sn0) / (se0 + 1e-16f);
    o.y = zd.y + fmaf(1e-7f, se1, sn1) / (se1 + 1e-16f);
    ((float2*)so)[(size_t)w * 32 + lane] = o;
}

// ---------------------------------------------------------------------------
// gemmT: encoder only ([N,128] @ [128,64] + bias -> zh)
// ---------------------------------------------------------------------------
#define GEMMT_U32 (2 * 128 * 68 + 2 * 4096 + 400)
#define GEMMT_SMEM (GEMMT_U32 * 4)
__global__ __launch_bounds__(256) void k_gemmT(
    const float* __restrict__ A, int mat,
    const float* __restrict__ bias, int N) {
    extern __shared__ u32 smu[];
    u32*   Ah  = smu;                       // 128*68
    u32*   Al  = Ah + 128 * 68;             // 128*68
    uint2* Bh  = (uint2*)(Al + 128 * 68);   // 2048 uint2
    uint2* Bl  = Bh + 2048;                 // 2048 uint2
    float* bs  = (float*)(Bl + 2048);       // 64
    int tid = threadIdx.x;
    int r0 = blockIdx.x * 128;
    {
        const float4* a4 = (const float4*)A;
        #pragma unroll
        for (int i = 0; i < 16; i++) {
            int idx = tid + i * 256;                // 128 rows x 32 f4
            int row = idx >> 5, c = idx & 31;
            int grow = min(r0 + row, N - 1);
            float4 v = __ldg(&a4[(size_t)grow * 32 + c]);
            u32 h0, l0, h1, l1;
            hsplit(v.x, v.y, h0, l0);
            hsplit(v.z, v.w, h1, l1);
            *(uint2*)&Ah[row * 68 + 2 * c] = make_uint2(h0, h1);
            *(uint2*)&Al[row * 68 + 2 * c] = make_uint2(l0, l1);
        }
        const uint4* ph = (const uint4*)g_bph[mat];
        const uint4* pl = (const uint4*)g_bpl[mat];
        uint4* dh = (uint4*)Bh;
        uint4* dl = (uint4*)Bl;
        #pragma unroll
        for (int i = 0; i < 4; i++) {
            dh[tid + i * 256] = __ldg(&ph[tid + i * 256]);
            dl[tid + i * 256] = __ldg(&pl[tid + i * 256]);
        }
        if (tid < 64) bs[tid] = bias[tid];
    }
    __syncthreads();
    int warp = tid >> 5, lane = tid & 31;
    int g = lane >> 2, t = lane & 3;
    int wm = warp * 16;
    float acc[8][4];
    #pragma unroll
    for (int nf = 0; nf < 8; nf++)
        #pragma unroll
        for (int c = 0; c < 4; c++) acc[nf][c] = 0.f;
    int b0 = (wm + g) * 68, b1 = (wm + 8 + g) * 68;
    #pragma unroll
    for (int ks = 0; ks < 8; ks++) {
        int kp = ks * 8 + t;
        u32 ah[4], al[4];
        ah[0] = Ah[b0 + kp];     ah[1] = Ah[b1 + kp];
        ah[2] = Ah[b0 + kp + 4]; ah[3] = Ah[b1 + kp + 4];
        al[0] = Al[b0 + kp];     al[1] = Al[b1 + kp];
        al[2] = Al[b0 + kp + 4]; al[3] = Al[b1 + kp + 4];
        #pragma unroll
        for (int nf = 0; nf < 8; nf++) {
            uint2 bh = Bh[(ks * 8 + nf) * 32 + lane];
            uint2 bl = Bl[(ks * 8 + nf) * 32 + lane];
            mmah(acc[nf], ah, bl.x, bl.y);
            mmah(acc[nf], al, bh.x, bh.y);
            mmah(acc[nf], ah, bh.x, bh.y);
        }
    }
    #pragma unroll
    for (int rs = 0; rs < 2; rs++) {
        int rr = r0 + wm + g + rs * 8;
        if (rr >= N) continue;
        #pragma unroll
        for (int nf = 0; nf < 8; nf++) {
            float2 bv = *(float2*)&bs[8 * nf + 2 * t];
            float y0 = acc[nf][rs * 2]     + bv.x;
            float y1 = acc[nf][rs * 2 + 1] + bv.y;
            g_zh[(size_t)rr * 32 + 4 * nf + t] = h2pack(y0, y1);
        }
    }
}

// ---------------------------------------------------------------------------
// k_mlp: FUSED mlp1 + mlp2 with register fragment handoff (r16, unchanged)
// ---------------------------------------------------------------------------
#define MLP_U32 (2 * 128 * 36 + 4 * 4096 + 384 + 192 + 208)
#define MLP_SMEM (MLP_U32 * 4)
__global__ __launch_bounds__(256, 2) void k_mlp(
    const float* __restrict__ A, int mat1, int mat2,
    const float* __restrict__ b1p, const float* __restrict__ g1p,
    const float* __restrict__ c1p, const float* __restrict__ b2p,
    const float* __restrict__ g2p, const float* __restrict__ c2p,
    const float* __restrict__ lw, const float* __restrict__ lhb,
    float* __restrict__ h_out, float* __restrict__ z_out,
    int N, int addres, int mode) {
    extern __shared__ u32 smu[];
    u32*   Ah  = smu;                        // 128*36
    u32*   Al  = Ah + 128 * 36;
    uint2* B1h = (uint2*)(Al + 128 * 36);    // 2048 uint2
    uint2* B1l = B1h + 2048;
    uint2* B2h = B1l + 2048;
    uint2* B2l = B2h + 2048;
    float* bs1 = (float*)(B2l + 2048);       // 128
    float* gs1 = bs1 + 128;
    float* cs1 = gs1 + 128;
    float* bs2 = cs1 + 128;                  // 64
    float* gs2 = bs2 + 64;
    float* cs2 = gs2 + 64;
    float* lws = cs2 + 64;                   // 208
    int tid = threadIdx.x;
    int r0 = blockIdx.x * 128;
    {
        const float4* a4 = (const float4*)A;
        #pragma unroll
        for (int i = 0; i < 8; i++) {
            int idx = tid + i * 256;                // 128 rows x 16 f4
            int row = idx >> 4, c = idx & 15;
            int grow = min(r0 + row, N - 1);
            float4 v = __ldg(&a4[(size_t)grow * 16 + c]);
            u32 h0, l0, h1, l1;
            hsplit(v.x, v.y, h0, l0);
            hsplit(v.z, v.w, h1, l1);
            *(uint2*)&Ah[row * 36 + 2 * c] = make_uint2(h0, h1);
            *(uint2*)&Al[row * 36 + 2 * c] = make_uint2(l0, l1);
        }
        const uint4* p1h = (const uint4*)g_bph[mat1];
        const uint4* p1l = (const uint4*)g_bpl[mat1];
        const uint4* p2h = (const uint4*)g_bph[mat2];
        const uint4* p2l = (const uint4*)g_bpl[mat2];
        #pragma unroll
        for (int i = 0; i < 4; i++) {
            ((uint4*)B1h)[tid + i * 256] = __ldg(&p1h[tid + i * 256]);
            ((uint4*)B1l)[tid + i * 256] = __ldg(&p1l[tid + i * 256]);
            ((uint4*)B2h)[tid + i * 256] = __ldg(&p2h[tid + i * 256]);
            ((uint4*)B2l)[tid + i * 256] = __ldg(&p2l[tid + i * 256]);
        }
        if (tid < 128) { bs1[tid] = b1p[tid]; gs1[tid] = g1p[tid]; cs1[tid] = c1p[tid]; }
        else if (tid < 192) {
            int k = tid - 128;
            bs2[k] = b2p[k];
            if (mode) { gs2[k] = g2p[k]; cs2[k] = c2p[k]; }
        }
        if (mode == 2 && tid >= 192 && tid < 240)
            ((float4*)lws)[tid - 192] = ((const float4*)lw)[tid - 192];
    }
    __syncthreads();
    int warp = tid >> 5, lane = tid & 31;
    int lg = lane >> 2, t = lane & 3;
    int wm = warp * 16;
    // ---- Phase 1: [128,64]@[64,128] ----
    float acc1[16][4];
    #pragma unroll
    for (int nf = 0; nf < 16; nf++)
        #pragma unroll
        for (int c = 0; c < 4; c++) acc1[nf][c] = 0.f;
    {
        int b0 = (wm + lg) * 36, b1 = (wm + 8 + lg) * 36;
        #pragma unroll
        for (int ks = 0; ks < 4; ks++) {
            int kp = ks * 8 + t;
            u32 ah[4], al[4];
            ah[0] = Ah[b0 + kp];     ah[1] = Ah[b1 + kp];
            ah[2] = Ah[b0 + kp + 4]; ah[3] = Ah[b1 + kp + 4];
            al[0] = Al[b0 + kp];     al[1] = Al[b1 + kp];
            al[2] = Al[b0 + kp + 4]; al[3] = Al[b1 + kp + 4];
            #pragma unroll
            for (int nf = 0; nf < 16; nf++) {
                uint2 bh = B1h[(ks * 16 + nf) * 32 + lane];
                uint2 bl = B1l[(ks * 16 + nf) * 32 + lane];
                mmah(acc1[nf], ah, bl.x, bl.y);
                mmah(acc1[nf], al, bh.x, bh.y);
                mmah(acc1[nf], ah, bh.x, bh.y);
            }
        }
    }
    // ---- Epilogue 1 -> phase2 A-fragment registers ----
    u32 fh[2][16], fl[2][16];
    #pragma unroll
    for (int rs = 0; rs < 2; rs++) {
        float y[32];
        #pragma unroll
        for (int nf = 0; nf < 16; nf++) {
            float2 bv = *(float2*)&bs1[8 * nf + 2 * t];
            y[2 * nf]     = acc1[nf][rs * 2]     + bv.x;
            y[2 * nf + 1] = acc1[nf][rs * 2 + 1] + bv.y;
        }
        float s = 0.f, q = 0.f;
        #pragma unroll
        for (int c = 0; c < 32; c++) { s += y[c]; q = fmaf(y[c], y[c], q); }
        s += __shfl_xor_sync(0xffffffffu, s, 1);
        q += __shfl_xor_sync(0xffffffffu, q, 1);
        s += __shfl_xor_sync(0xffffffffu, s, 2);
        q += __shfl_xor_sync(0xffffffffu, q, 2);
        float mu = s * (1.f / 128.f);
        float var = q * (1.f / 128.f) - mu * mu;
        float rsv = rsqrtf(var + 1e-5f);
        #pragma unroll
        for (int nf = 0; nf < 16; nf++) {
            float2 gv = *(float2*)&gs1[8 * nf + 2 * t];
            float2 cv = *(float2*)&cs1[8 * nf + 2 * t];
            float o0 = fmaxf((y[2 * nf]     - mu) * rsv * gv.x + cv.x, 0.f);
            float o1 = fmaxf((y[2 * nf + 1] - mu) * rsv * gv.y + cv.y, 0.f);
            hsplit(o0, o1, fh[rs][nf], fl[rs][nf]);
        }
    }
    // ---- Phase 2: [128,128]@[128,64], A-frags from registers ----
    float acc2[8][4];
    #pragma unroll
    for (int nf = 0; nf < 8; nf++)
        #pragma unroll
        for (int c = 0; c < 4; c++) acc2[nf][c] = 0.f;
    #pragma unroll
    for (int ks = 0; ks < 8; ks++) {
        u32 ah[4], al[4];
        ah[0] = fh[0][2 * ks];     ah[1] = fh[1][2 * ks];
        ah[2] = fh[0][2 * ks + 1]; ah[3] = fh[1][2 * ks + 1];
        al[0] = fl[0][2 * ks];     al[1] = fl[1][2 * ks];
        al[2] = fl[0][2 * ks + 1]; al[3] = fl[1][2 * ks + 1];
        #pragma unroll
        for (int nf = 0; nf < 8; nf++) {
            uint2 bh = B2h[(ks * 8 + nf) * 32 + lane];
            uint2 bl = B2l[(ks * 8 + nf) * 32 + lane];
            mmah(acc2[nf], ah, bl.x, bl.y);
            mmah(acc2[nf], al, bh.x, bh.y);
            mmah(acc2[nf], ah, bh.x, bh.y);
        }
    }
    // ---- Epilogue 2 ----
    #pragma unroll
    for (int rs = 0; rs < 2; rs++) {
        int rr = r0 + wm + lg + rs * 8;
        bool ok = rr < N;
        float y[16];
        #pragma unroll
        for (int nf = 0; nf < 8; nf++) {
            float2 bv = *(float2*)&bs2[8 * nf + 2 * t];
            y[2 * nf]     = acc2[nf][rs * 2]     + bv.x;
            y[2 * nf + 1] = acc2[nf][rs * 2 + 1] + bv.y;
        }
        if (addres && ok) {
            #pragma unroll
            for (int nf = 0; nf < 8; nf++) {
                float2 h = ((const float2*)h_out)[(size_t)rr * 32 + 4 * nf + t];
                y[2 * nf] += h.x; y[2 * nf + 1] += h.y;
            }
        }
        if (mode == 1 && ok) {
            #pragma unroll
            for (int nf = 0; nf < 8; nf++) {
                float2 v; v.x = y[2 * nf]; v.y = y[2 * nf + 1];
                ((float2*)h_out)[(size_t)rr * 32 + 4 * nf + t] = v;
            }
        }
        float s = 0.f, q = 0.f;
        #pragma unroll
        for (int c = 0; c < 16; c++) { s += y[c]; q = fmaf(y[c], y[c], q); }
        s += __shfl_xor_sync(0xffffffffu, s, 1);
        q += __shfl_xor_sync(0xffffffffu, q, 1);
        s += __shfl_xor_sync(0xffffffffu, s, 2);
        q += __shfl_xor_sync(0xffffffffu, q, 2);
        float mu = s * (1.f / 64.f);
        float var = q * (1.f / 64.f) - mu * mu;
        float rsv = rsqrtf(var + 1e-5f);
        float o16[16];
        #pragma unroll
        for (int nf = 0; nf < 8; nf++) {
            float2 gv = *(float2*)&gs2[8 * nf + 2 * t];
            float2 cv = *(float2*)&cs2[8 * nf + 2 * t];
            o16[2 * nf]     = fmaxf((y[2 * nf]     - mu) * rsv * gv.x + cv.x, 0.f);
            o16[2 * nf + 1] = fmaxf((y[2 * nf + 1] - mu) * rsv * gv.y + cv.y, 0.f);
        }
        if (mode == 1) {
            if (ok) {
                #pragma unroll
                for (int nf = 0; nf < 8; nf++)
                    g_zh[(size_t)rr * 32 + 4 * nf + t] = h2pack(o16[2 * nf], o16[2 * nf + 1]);
            }
        } else {  // mode 2: final out + head
            if (ok) {
                #pragma unroll
                for (int nf = 0; nf < 8; nf++) {
                    float2 v; v.x = o16[2 * nf]; v.y = o16[2 * nf + 1];
                    ((float2*)z_out)[(size_t)rr * 32 + 4 * nf + t] = v;
                }
            }
            float p0 = 0.f, p1 = 0.f, p2 = 0.f;
            #pragma unroll
            for (int nf = 0; nf < 8; nf++) {
                int c0 = 8 * nf + 2 * t, c1 = c0 + 1;
                p0 = fmaf(o16[2 * nf], lws[c0 * 3 + 0], p0);
                p1 = fmaf(o16[2 * nf], lws[c0 * 3 + 1], p1);
                p2 = fmaf(o16[2 * nf], lws[c0 * 3 + 2], p2);
                p0 = fmaf(o16[2 * nf + 1], lws[c1 * 3 + 0], p0);
                p1 = fmaf(o16[2 * nf + 1], lws[c1 * 3 + 1], p1);
                p2 = fmaf(o16[2 * nf + 1], lws[c1 * 3 + 2], p2);
            }
            p0 += __shfl_xor_sync(0xffffffffu, p0, 1);
            p1 += __shfl_xor_sync(0xffffffffu, p1, 1);
            p2 += __shfl_xor_sync(0xffffffffu, p2, 1);
            p0 += __shfl_xor_sync(0xffffffffu, p0, 2);
            p1 += __shfl_xor_sync(0xffffffffu, p1, 2);
            p2 += __shfl_xor_sync(0xffffffffu, p2, 2);
            if (t == 0 && ok) {
                size_t base = (size_t)N * 64 + (size_t)rr * 3;
                z_out[base + 0] = p0 + __ldg(lhb + 0);
                z_out[base + 1] = p1 + __ldg(lhb + 1);
                z_out[base + 2] = p2 + __ldg(lhb + 2);
            }
        }
    }
}

// ---------------------------------------------------------------------------
// Host launch
// ---------------------------------------------------------------------------
extern "C" void kernel_launch(void* const* d_in, const int* in_sizes, int n_in,
                              void* d_out, int out_size) {
    const float* x    = (const float*)d_in[0];
    const void*  ei   = d_in[1];
    const float* encW = (const float*)d_in[2];
    const float* encB = (const float*)d_in[3];
    const float* t    = (const float*)d_in[4];
    const float* W1   = (const float*)d_in[5];
    const float* b1   = (const float*)d_in[6];
    const float* g1   = (const float*)d_in[7];
    const float* bb1  = (const float*)d_in[8];
    const float* W2   = (const float*)d_in[9];
    const float* b2   = (const float*)d_in[10];
    const float* ng   = (const float*)d_in[11];
    const float* nb   = (const float*)d_in[12];
    const float* lw   = (const float*)d_in[13];
    const float* lb   = (const float*)d_in[14];
    int N = in_sizes[0] / 128;
    int E = in_sizes[1] / 2;
    if (N > NMAX) N = NMAX;
    if (E > EMAX) E = EMAX;
    float* out = (float*)d_out;

    cudaFuncSetAttribute(k_mlp,   cudaFuncAttributeMaxDynamicSharedMemorySize, MLP_SMEM);
    cudaFuncSetAttribute(k_gemmT, cudaFuncAttributeMaxDynamicSharedMemorySize, GEMMT_SMEM);

    float *gh, *gsv;
    int *gdeg;
    cudaGetSymbolAddress((void**)&gh,   g_h);
    cudaGetSymbolAddress((void**)&gsv,  g_s);
    cudaGetSymbolAddress((void**)&gdeg, g_deg);

    int eb4     = (E + 1023) / 1024;
    int rowsW   = (N + 7) / 8;
    int tilesB  = (N + 127) / 128;
    int sblocks = (N + 1023) / 1024;

    // edge preprocessing (CSR by dst) + fused weight packing
    cudaMemsetAsync(gdeg, 0, (size_t)N * sizeof(int));
    k_normpack<<<eb4 + 7, 256>>>(ei, E, encW, W1, W2);
    k_scan<<<sblocks, 1024>>>(N);
    k_scatter<<<eb4, 256>>>(E);

    // encoder: x @ encW + encB -> zh (mat 0)
    k_gemmT<<<tilesB, 256, GEMMT_SMEM>>>(x, 0, encB, N);

    for (int i = 0; i < 3; i++) {
        k_aggr<<<rowsW, 256>>>(t, i, gsv, N);
        if (i < 2) {
            k_mlp<<<tilesB, 256, MLP_SMEM>>>(gsv, 4 + i, 1 + i,
                                             b1 + i * 128, g1 + i * 128, bb1 + i * 128,
                                             b2 + i * 64, ng + (i + 1) * 64, nb + (i + 1) * 64,
                                             nullptr, nullptr, gh, nullptr,
                                             N, i ? 1 : 0, 1);
        } else {
            k_mlp<<<tilesB, 256, MLP_SMEM>>>(gsv, 4 + i, 1 + i,
                                             b1 + i * 128, g1 + i * 128, bb1 + i * 128,
                                             b2 + i * 64, ng, nb,
                                             lw, lb, gh, out, N, 1, 2);
        }
    }
}